// round 2
// baseline (speedup 1.0000x reference)
#include <cuda_runtime.h>
#include <math.h>

#define Bc 4
#define Cc 128
#define Dc 64
#define Nc 2048
#define Mc 2048
#define Hc 256
#define Kc 16
#define NPTS (Bc*Nc*Kc)   // 131072
#define EPSf 1e-5f

// ---------------- scratch (static device globals; allocation-free) ----------
__device__ __align__(256) float g_q[Bc*Nc*Dc];
__device__ __align__(256) float g_k[Bc*Mc*Dc];
__device__ __align__(256) float g_v[Bc*Mc*Dc];
__device__ __align__(256) int   g_idx[NPTS];
__device__ __align__(256) float g_pe[NPTS*Dc];            // pe1 then pe (in place)
__device__ __align__(256) float g_a1[(size_t)NPTS*Hc];    // 134 MB
__device__ __align__(256) float g_a2[NPTS*Dc];
__device__ __align__(256) float g_agg[Bc*Nc*Dc];
__device__ double g_sum1[Dc], g_sq1[Dc];
__device__ double g_sum2[Hc], g_sq2[Hc];
__device__ float g_mean1[Dc], g_rstd1[Dc];
__device__ float g_mean2[Hc], g_rstd2[Hc];

// ---------------- zero stats --------------------------------------------
__global__ void zero_stats_kernel() {
    int t = threadIdx.x;
    if (t < Dc) { g_sum1[t] = 0.0; g_sq1[t] = 0.0; }
    if (t < Hc) { g_sum2[t] = 0.0; g_sq2[t] = 0.0; }
}

// ---------------- q/k/v 1x1 convs ----------------------------------------
// out layout: (b, point, d), d contiguous
__global__ void qkv_kernel(const float* __restrict__ fq, const float* __restrict__ fs,
                           const float* __restrict__ Wq, const float* __restrict__ bq,
                           const float* __restrict__ Wk, const float* __restrict__ bk,
                           const float* __restrict__ Wv, const float* __restrict__ bv) {
    __shared__ float sWt[Cc*Dc];  // transposed [c][d]
    __shared__ float sb[Dc];
    int which = blockIdx.z % 3, b = blockIdx.z / 3;
    const float* f    = (which == 0) ? fq : fs;
    const float* W    = (which == 0) ? Wq : (which == 1 ? Wk : Wv);
    const float* bias = (which == 0) ? bq : (which == 1 ? bk : bv);
    float* out        = (which == 0) ? g_q : (which == 1 ? g_k : g_v);
    for (int i = threadIdx.x; i < Cc*Dc; i += blockDim.x) {
        int d = i / Cc, c = i % Cc;
        sWt[c*Dc + d] = W[i];
    }
    for (int i = threadIdx.x; i < Dc; i += blockDim.x) sb[i] = bias[i];
    __syncthreads();
    int n = blockIdx.x * blockDim.x + threadIdx.x;
    const float* fb = f + (size_t)b*Cc*Nc + n;
    float acc[Dc];
    #pragma unroll
    for (int d = 0; d < Dc; d++) acc[d] = sb[d];
    for (int c = 0; c < Cc; c++) {
        float fv = fb[(size_t)c*Nc];
        const float4* wr = (const float4*)(sWt + c*Dc);
        #pragma unroll
        for (int d4 = 0; d4 < Dc/4; d4++) {
            float4 w = wr[d4];
            acc[d4*4+0] = fmaf(w.x, fv, acc[d4*4+0]);
            acc[d4*4+1] = fmaf(w.y, fv, acc[d4*4+1]);
            acc[d4*4+2] = fmaf(w.z, fv, acc[d4*4+2]);
            acc[d4*4+3] = fmaf(w.w, fv, acc[d4*4+3]);
        }
    }
    float4* o = (float4*)(out + ((size_t)b*Nc + n)*Dc);
    #pragma unroll
    for (int d4 = 0; d4 < Dc/4; d4++)
        o[d4] = make_float4(acc[d4*4], acc[d4*4+1], acc[d4*4+2], acc[d4*4+3]);
}

// ---------------- KNN ------------------------------------------------------
__global__ void knn_kernel(const float* __restrict__ pq, const float* __restrict__ ps) {
    __shared__ float sx[Mc], sy[Mc], sz[Mc], ss[Mc];
    int b = blockIdx.y;
    const float* p = ps + (size_t)b*3*Mc;
    for (int i = threadIdx.x; i < Mc; i += blockDim.x) {
        float x = p[i], y = p[Mc + i], z = p[2*Mc + i];
        sx[i] = x; sy[i] = y; sz[i] = z; ss[i] = x*x + y*y + z*z;
    }
    __syncthreads();
    int n = blockIdx.x * blockDim.x + threadIdx.x;
    const float* pqb = pq + (size_t)b*3*Nc;
    float qx = pqb[n], qy = pqb[Nc + n], qz = pqb[2*Nc + n];
    float qq = qx*qx + qy*qy + qz*qz;
    float bd[Kc]; int bi[Kc];
    #pragma unroll
    for (int j = 0; j < Kc; j++) { bd[j] = 3.4e38f; bi[j] = 0; }
    float worst = 3.4e38f; int wpos = 0;
    for (int m = 0; m < Mc; m++) {
        float dot = qx*sx[m] + qy*sy[m] + qz*sz[m];
        float d2 = qq + ss[m] - 2.0f*dot;   // same formula as reference
        if (d2 < worst) {
            #pragma unroll
            for (int j = 0; j < Kc; j++) if (j == wpos) { bd[j] = d2; bi[j] = m; }
            worst = -3.4e38f;
            #pragma unroll
            for (int j = 0; j < Kc; j++) if (bd[j] > worst) { worst = bd[j]; wpos = j; }
        }
    }
    int* o = g_idx + ((size_t)b*Nc + n)*Kc;
    #pragma unroll
    for (int j = 0; j < Kc; j++) o[j] = bi[j];
}

// ---------------- pe1 = Wp1 @ pos_rel + bp1 -------------------------------
__global__ void pe1_kernel(const float* __restrict__ pq, const float* __restrict__ ps,
                           const float* __restrict__ Wp1, const float* __restrict__ bp1) {
    __shared__ float srel[64][3];
    int p0 = blockIdx.x * 64;
    int t = threadIdx.x;
    if (t < 64) {
        int p = p0 + t;
        int b = p / (Nc*Kc);
        int rem = p % (Nc*Kc);
        int n = rem / Kc;
        int iv = g_idx[p];
        const float* pqb = pq + (size_t)b*3*Nc;
        const float* psb = ps + (size_t)b*3*Mc;
        srel[t][0] = pqb[n]        - psb[iv];
        srel[t][1] = pqb[Nc + n]   - psb[Mc + iv];
        srel[t][2] = pqb[2*Nc + n] - psb[2*Mc + iv];
    }
    __syncthreads();
    int d = t & 63, slot = t >> 6;
    float w0 = Wp1[d*3], w1 = Wp1[d*3+1], w2 = Wp1[d*3+2], bb = bp1[d];
    for (int i = slot; i < 64; i += 4) {
        float x = fmaf(w0, srel[i][0], fmaf(w1, srel[i][1], fmaf(w2, srel[i][2], bb)));
        g_pe[(size_t)(p0 + i)*Dc + d] = x;
    }
}

// ---------------- per-channel stats (for train-mode BN) --------------------
__global__ void stats_kernel(int which) {
    const float* data; int nch; double* sum; double* sq;
    if (which == 0) { data = g_pe; nch = Dc; sum = g_sum1; sq = g_sq1; }
    else            { data = g_a1; nch = Hc; sum = g_sum2; sq = g_sq2; }
    int ch   = threadIdx.x % nch;
    int rows = 256 / nch;
    long r0   = (long)blockIdx.x*rows + threadIdx.x / nch;
    long step = (long)gridDim.x*rows;
    double s = 0.0, s2 = 0.0;
    for (long p = r0; p < NPTS; p += step) {
        float x = data[p*nch + ch];
        s  += x;
        s2 += (double)x * (double)x;
    }
    atomicAdd(&sum[ch], s);
    atomicAdd(&sq[ch],  s2);
}

__global__ void finalize_kernel(int which) {
    int c = threadIdx.x;
    const double inv = 1.0 / (double)NPTS;
    if (which == 0) {
        if (c < Dc) {
            double m = g_sum1[c]*inv;
            double v = g_sq1[c]*inv - m*m;
            g_mean1[c] = (float)m;
            g_rstd1[c] = rsqrtf((float)v + EPSf);
        }
    } else {
        if (c < Hc) {
            double m = g_sum2[c]*inv;
            double v = g_sq2[c]*inv - m*m;
            g_mean2[c] = (float)m;
            g_rstd2[c] = rsqrtf((float)v + EPSf);
        }
    }
}

// ---------------- pe = Wp2 @ relu(BN1(pe1)) + bp2 ; a1 = Wa1 @ (qk_rel+pe) + ba1
__global__ void pe2_a1_kernel(const float* __restrict__ Wp2, const float* __restrict__ bp2,
                              const float* __restrict__ gp,  const float* __restrict__ btp,
                              const float* __restrict__ Wa1, const float* __restrict__ ba1) {
    extern __shared__ float sm6[];
    float* sWp2t  = sm6;                  // Dc*Dc  (transposed [e][d])
    float* sWa1t  = sWp2t + Dc*Dc;        // Dc*Hc  (transposed [e][h])
    float* sX     = sWa1t + Dc*Hc;        // 256*Dc thread-private columns
    float* sbn    = sX + 256*Dc;          // Dc scale
    float* sshift = sbn + Dc;             // Dc shift
    float* sbp2   = sshift + Dc;          // Dc
    float* sba1   = sbp2 + Dc;            // Hc
    int t = threadIdx.x;
    for (int i = t; i < Dc*Dc; i += blockDim.x) {
        int d = i / Dc, e = i % Dc;
        sWp2t[e*Dc + d] = Wp2[i];
    }
    for (int i = t; i < Hc*Dc; i += blockDim.x) {
        int h = i / Dc, e = i % Dc;
        sWa1t[e*Hc + h] = Wa1[i];
    }
    for (int i = t; i < Dc; i += blockDim.x) {
        float sc = gp[i] * g_rstd1[i];
        sbn[i] = sc;
        sshift[i] = btp[i] - g_mean1[i]*sc;
        sbp2[i] = bp2[i];
    }
    for (int i = t; i < Hc; i += blockDim.x) sba1[i] = ba1[i];
    __syncthreads();

    int pt = blockIdx.x * blockDim.x + t;
    int b  = pt / (Nc*Kc);
    int rem = pt % (Nc*Kc);
    int n  = rem / Kc;
    int iv = g_idx[pt];
    float* pe = g_pe + (size_t)pt*Dc;

    // BN1 + relu into thread-private smem column
    const float4* pe4 = (const float4*)pe;
    #pragma unroll
    for (int e4 = 0; e4 < Dc/4; e4++) {
        float4 v = pe4[e4];
        int e = e4*4;
        sX[(e+0)*256 + t] = fmaxf(fmaf(v.x, sbn[e+0], sshift[e+0]), 0.f);
        sX[(e+1)*256 + t] = fmaxf(fmaf(v.y, sbn[e+1], sshift[e+1]), 0.f);
        sX[(e+2)*256 + t] = fmaxf(fmaf(v.z, sbn[e+2], sshift[e+2]), 0.f);
        sX[(e+3)*256 + t] = fmaxf(fmaf(v.w, sbn[e+3], sshift[e+3]), 0.f);
    }

    // pe2: full 64-wide matvec, acc in regs
    float acc[Dc];
    #pragma unroll
    for (int j = 0; j < Dc; j++) acc[j] = sbp2[j];
    for (int e = 0; e < Dc; e++) {
        float xv = sX[e*256 + t];
        const float4* wr = (const float4*)(sWp2t + e*Dc);
        #pragma unroll
        for (int j4 = 0; j4 < Dc/4; j4++) {
            float4 w = wr[j4];
            acc[j4*4+0] = fmaf(w.x, xv, acc[j4*4+0]);
            acc[j4*4+1] = fmaf(w.y, xv, acc[j4*4+1]);
            acc[j4*4+2] = fmaf(w.z, xv, acc[j4*4+2]);
            acc[j4*4+3] = fmaf(w.w, xv, acc[j4*4+3]);
        }
    }

    // write pe (in place) and build s = pe + q - k in sX
    const float* qp = g_q + ((size_t)b*Nc + n)*Dc;
    const float* kp = g_k + ((size_t)b*Mc + iv)*Dc;
    #pragma unroll
    for (int j4 = 0; j4 < Dc/4; j4++) {
        int d = j4*4;
        float4 qv = *(const float4*)(qp + d);
        float4 kv = *(const float4*)(kp + d);
        float4 o = make_float4(acc[d], acc[d+1], acc[d+2], acc[d+3]);
        ((float4*)pe)[j4] = o;
        sX[(d+0)*256 + t] = o.x + qv.x - kv.x;
        sX[(d+1)*256 + t] = o.y + qv.y - kv.y;
        sX[(d+2)*256 + t] = o.z + qv.z - kv.z;
        sX[(d+3)*256 + t] = o.w + qv.w - kv.w;
    }

    // a1 = Wa1 @ s + ba1, 8 chunks of 32 outputs
    float* a1p = g_a1 + (size_t)pt*Hc;
    for (int hc = 0; hc < 8; hc++) {
        float a[32];
        #pragma unroll
        for (int j = 0; j < 32; j++) a[j] = sba1[hc*32 + j];
        for (int e = 0; e < Dc; e++) {
            float sv = sX[e*256 + t];
            const float4* wr = (const float4*)(sWa1t + e*Hc + hc*32);
            #pragma unroll
            for (int j4 = 0; j4 < 8; j4++) {
                float4 w = wr[j4];
                a[j4*4+0] = fmaf(w.x, sv, a[j4*4+0]);
                a[j4*4+1] = fmaf(w.y, sv, a[j4*4+1]);
                a[j4*4+2] = fmaf(w.z, sv, a[j4*4+2]);
                a[j4*4+3] = fmaf(w.w, sv, a[j4*4+3]);
            }
        }
        float4* op = (float4*)(a1p + hc*32);
        #pragma unroll
        for (int j4 = 0; j4 < 8; j4++)
            op[j4] = make_float4(a[j4*4], a[j4*4+1], a[j4*4+2], a[j4*4+3]);
    }
}

// ---------------- a2 = Wa2 @ relu(BN2(a1)) + ba2 ---------------------------
__global__ void a2_kernel(const float* __restrict__ Wa2, const float* __restrict__ ba2,
                          const float* __restrict__ ga,  const float* __restrict__ bta) {
    extern __shared__ float sm7[];
    float* sWa2t   = sm7;                 // Hc*Dc (transposed [h][d])
    float* sA      = sWa2t + Hc*Dc;       // 64*256 thread-private columns
    float* sscale  = sA + 256*Dc;         // Hc
    float* sshift2 = sscale + Hc;         // Hc
    float* sba2    = sshift2 + Hc;        // Dc
    int t = threadIdx.x;
    for (int i = t; i < Dc*Hc; i += blockDim.x) {
        int d = i / Hc, h = i % Hc;
        sWa2t[h*Dc + d] = Wa2[i];
    }
    for (int i = t; i < Hc; i += blockDim.x) {
        float sc = ga[i] * g_rstd2[i];
        sscale[i] = sc;
        sshift2[i] = bta[i] - g_mean2[i]*sc;
    }
    for (int i = t; i < Dc; i += blockDim.x) sba2[i] = ba2[i];
    __syncthreads();

    int pt = blockIdx.x * blockDim.x + t;
    const float* a1p = g_a1 + (size_t)pt*Hc;
    float acc[Dc];
    #pragma unroll
    for (int j = 0; j < Dc; j++) acc[j] = sba2[j];

    for (int hc = 0; hc < 4; hc++) {
        // load 64-h chunk, BN2+relu into thread column
        const float4* ap = (const float4*)(a1p + hc*64);
        #pragma unroll
        for (int h4 = 0; h4 < 16; h4++) {
            float4 v = ap[h4];
            int hg = hc*64 + h4*4;
            int hl = h4*4;
            sA[(hl+0)*256 + t] = fmaxf(fmaf(v.x, sscale[hg+0], sshift2[hg+0]), 0.f);
            sA[(hl+1)*256 + t] = fmaxf(fmaf(v.y, sscale[hg+1], sshift2[hg+1]), 0.f);
            sA[(hl+2)*256 + t] = fmaxf(fmaf(v.z, sscale[hg+2], sshift2[hg+2]), 0.f);
            sA[(hl+3)*256 + t] = fmaxf(fmaf(v.w, sscale[hg+3], sshift2[hg+3]), 0.f);
        }
        for (int hl = 0; hl < 64; hl++) {
            float av = sA[hl*256 + t];
            int h = hc*64 + hl;
            const float4* wr = (const float4*)(sWa2t + h*Dc);
            #pragma unroll
            for (int j4 = 0; j4 < Dc/4; j4++) {
                float4 w = wr[j4];
                acc[j4*4+0] = fmaf(w.x, av, acc[j4*4+0]);
                acc[j4*4+1] = fmaf(w.y, av, acc[j4*4+1]);
                acc[j4*4+2] = fmaf(w.z, av, acc[j4*4+2]);
                acc[j4*4+3] = fmaf(w.w, av, acc[j4*4+3]);
            }
        }
    }
    float4* o = (float4*)(g_a2 + (size_t)pt*Dc);
    #pragma unroll
    for (int j4 = 0; j4 < Dc/4; j4++)
        o[j4] = make_float4(acc[j4*4], acc[j4*4+1], acc[j4*4+2], acc[j4*4+3]);
}

// ---------------- softmax over K + aggregate --------------------------------
__global__ void softagg_kernel() {
    int t = threadIdx.x;
    int d = t & 63;
    int bn = blockIdx.x*4 + (t >> 6);
    int b = bn / Nc;
    const int* ip = g_idx + (size_t)bn*Kc;
    float av[Kc];
    float mx = -3.4e38f;
    #pragma unroll
    for (int k = 0; k < Kc; k++) {
        av[k] = g_a2[((size_t)bn*Kc + k)*Dc + d];
        mx = fmaxf(mx, av[k]);
    }
    float sum = 0.f;
    #pragma unroll
    for (int k = 0; k < Kc; k++) { av[k] = expf(av[k] - mx); sum += av[k]; }
    float inv = 1.f / sum;
    float agg = 0.f;
    #pragma unroll
    for (int k = 0; k < Kc; k++) {
        int iv = ip[k];
        float vg = g_v[((size_t)b*Mc + iv)*Dc + d];
        float pe = g_pe[((size_t)bn*Kc + k)*Dc + d];
        agg = fmaf(av[k]*inv, vg + pe, agg);
    }
    g_agg[(size_t)bn*Dc + d] = agg;
}

// ---------------- out = We @ agg + be + fq ---------------------------------
__global__ void final_kernel(const float* __restrict__ We, const float* __restrict__ be,
                             const float* __restrict__ fq, float* __restrict__ out) {
    __shared__ float sWt[Dc*64];   // transposed [d][cj] for this half
    int half = blockIdx.y, b = blockIdx.z;
    for (int i = threadIdx.x; i < 64*Dc; i += blockDim.x) {
        int cj = i / Dc, d = i % Dc;
        sWt[d*64 + cj] = We[(half*64 + cj)*Dc + d];
    }
    __syncthreads();
    int n = blockIdx.x * blockDim.x + threadIdx.x;
    const float* ag = g_agg + ((size_t)b*Nc + n)*Dc;
    float acc[64];
    #pragma unroll
    for (int j = 0; j < 64; j++) acc[j] = 0.f;
    for (int d = 0; d < Dc; d++) {
        float av = ag[d];
        const float4* wr = (const float4*)(sWt + d*64);
        #pragma unroll
        for (int j4 = 0; j4 < 16; j4++) {
            float4 w = wr[j4];
            acc[j4*4+0] = fmaf(w.x, av, acc[j4*4+0]);
            acc[j4*4+1] = fmaf(w.y, av, acc[j4*4+1]);
            acc[j4*4+2] = fmaf(w.z, av, acc[j4*4+2]);
            acc[j4*4+3] = fmaf(w.w, av, acc[j4*4+3]);
        }
    }
    for (int j = 0; j < 64; j++) {
        int c = half*64 + j;
        size_t o = (size_t)b*Cc*Nc + (size_t)c*Nc + n;
        out[o] = acc[j] + be[c] + fq[o];
    }
}

// ---------------- launch -----------------------------------------------------
extern "C" void kernel_launch(void* const* d_in, const int* in_sizes, int n_in,
                              void* d_out, int out_size) {
    const float* pq  = (const float*)d_in[0];
    const float* fq  = (const float*)d_in[1];
    const float* ps  = (const float*)d_in[2];
    const float* fs  = (const float*)d_in[3];
    const float* Wq  = (const float*)d_in[4];  const float* bq  = (const float*)d_in[5];
    const float* Wk  = (const float*)d_in[6];  const float* bk  = (const float*)d_in[7];
    const float* Wv  = (const float*)d_in[8];  const float* bv  = (const float*)d_in[9];
    const float* Wp1 = (const float*)d_in[10]; const float* bp1 = (const float*)d_in[11];
    const float* gp  = (const float*)d_in[12]; const float* btp = (const float*)d_in[13];
    const float* Wp2 = (const float*)d_in[14]; const float* bp2 = (const float*)d_in[15];
    const float* Wa1 = (const float*)d_in[16]; const float* ba1 = (const float*)d_in[17];
    const float* ga  = (const float*)d_in[18]; const float* bta = (const float*)d_in[19];
    const float* Wa2 = (const float*)d_in[20]; const float* ba2 = (const float*)d_in[21];
    const float* We  = (const float*)d_in[22]; const float* be  = (const float*)d_in[23];
    float* out = (float*)d_out;

    const int SMEM6 = (Dc*Dc + Dc*Hc + 256*Dc + Dc + Dc + Dc + Hc) * (int)sizeof(float);
    const int SMEM7 = (Hc*Dc + 256*Dc + Hc + Hc + Dc) * (int)sizeof(float);
    cudaFuncSetAttribute(pe2_a1_kernel, cudaFuncAttributeMaxDynamicSharedMemorySize, SMEM6);
    cudaFuncSetAttribute(a2_kernel,     cudaFuncAttributeMaxDynamicSharedMemorySize, SMEM7);

    zero_stats_kernel<<<1, 256>>>();
    qkv_kernel<<<dim3(Nc/128, 1, Bc*3), 128>>>(fq, fs, Wq, bq, Wk, bk, Wv, bv);
    knn_kernel<<<dim3(Nc/256, Bc), 256>>>(pq, ps);
    pe1_kernel<<<NPTS/64, 256>>>(pq, ps, Wp1, bp1);
    stats_kernel<<<512, 256>>>(0);
    finalize_kernel<<<1, 256>>>(0);
    pe2_a1_kernel<<<NPTS/256, 256, SMEM6>>>(Wp2, bp2, gp, btp, Wa1, ba1);
    stats_kernel<<<512, 256>>>(1);
    finalize_kernel<<<1, 256>>>(1);
    a2_kernel<<<NPTS/256, 256, SMEM7>>>(Wa2, ba2, ga, bta);
    softagg_kernel<<<(Bc*Nc)/4, 256>>>();
    final_kernel<<<dim3(Nc/128, 2, Bc), 128>>>(We, be, fq, out);
}

// round 3
// speedup vs baseline: 1.5847x; 1.5847x over previous
#include <cuda_runtime.h>
#include <math.h>

#define Bc 4
#define Cc 128
#define Dc 64
#define Nc 2048
#define Mc 2048
#define Hc 256
#define Kc 16
#define NPTS (Bc*Nc*Kc)   // 131072
#define EPSf 1e-5f

// ---------------- scratch (static device globals; allocation-free) ----------
__device__ __align__(256) float g_q[Bc*Nc*Dc];
__device__ __align__(256) float g_k[Bc*Mc*Dc];
__device__ __align__(256) float g_v[Bc*Mc*Dc];
__device__ __align__(256) int   g_idx[NPTS];
__device__ __align__(256) float g_pe[NPTS*Dc];            // pe1 then pe (in place)
__device__ __align__(256) float g_a1[(size_t)NPTS*Hc];    // 134 MB, layout [h][pt]
__device__ __align__(256) float g_agg[Bc*Nc*Dc];
__device__ double g_sum1[Dc], g_sq1[Dc];
__device__ double g_sum2[Hc], g_sq2[Hc];
__device__ float g_mean1[Dc], g_rstd1[Dc];
__device__ float g_mean2[Hc], g_rstd2[Hc];

// ---------------- zero stats ------------------------------------------------
__global__ void zero_stats_kernel() {
    int t = threadIdx.x;
    if (t < Dc) { g_sum1[t] = 0.0; g_sq1[t] = 0.0; }
    if (t < Hc) { g_sum2[t] = 0.0; g_sq2[t] = 0.0; }
}

// ---------------- q/k/v 1x1 convs as tiled GEMM ----------------------------
// out layout: (b, point, d), d contiguous. Block: 128 n x 64 d, 512 threads.
__global__ __launch_bounds__(512, 2)
void qkv_kernel(const float* __restrict__ fq, const float* __restrict__ fs,
                const float* __restrict__ Wq, const float* __restrict__ bq,
                const float* __restrict__ Wk, const float* __restrict__ bk,
                const float* __restrict__ Wv, const float* __restrict__ bv) {
    extern __shared__ float sm0[];
    float* sW = sm0;            // [64 d][128 c] natural
    float* sF = sW + Dc*Cc;     // [32 c][128 n] stage
    float* sb = sF + 32*128;    // 64
    int zw = blockIdx.y;
    int which = zw >> 2, b = zw & 3;
    const float* f    = (which == 0) ? fq : fs;
    const float* W    = (which == 0) ? Wq : (which == 1 ? Wk : Wv);
    const float* bias = (which == 0) ? bq : (which == 1 ? bk : bv);
    float* out        = (which == 0) ? g_q : (which == 1 ? g_k : g_v);
    int t = threadIdx.x;
    for (int i = t; i < Dc*Cc; i += 512) sW[i] = W[i];
    if (t < Dc) sb[t] = bias[t];
    int nblk = blockIdx.x * 128;
    const float* fb = f + (size_t)b*Cc*Nc + nblk;
    int og = t >> 5, pg = t & 31;
    int d0 = og*4, n0 = pg*4;
    float acc[4][4];
    #pragma unroll
    for (int q = 0; q < 4; q++)
        #pragma unroll
        for (int j = 0; j < 4; j++) acc[q][j] = 0.f;
    for (int ks = 0; ks < 4; ks++) {
        int c0 = ks*32;
        __syncthreads();
        for (int i = t; i < 32*128; i += 512) {
            int cl = i >> 7, nl = i & 127;
            sF[cl*128 + nl] = fb[(size_t)(c0 + cl)*Nc + nl];
        }
        __syncthreads();
        #pragma unroll 4
        for (int cl = 0; cl < 32; cl++) {
            float4 x4 = *(const float4*)&sF[cl*128 + n0];
            float w0 = sW[(d0+0)*Cc + c0 + cl];
            float w1 = sW[(d0+1)*Cc + c0 + cl];
            float w2 = sW[(d0+2)*Cc + c0 + cl];
            float w3 = sW[(d0+3)*Cc + c0 + cl];
            acc[0][0] = fmaf(w0, x4.x, acc[0][0]); acc[0][1] = fmaf(w0, x4.y, acc[0][1]);
            acc[0][2] = fmaf(w0, x4.z, acc[0][2]); acc[0][3] = fmaf(w0, x4.w, acc[0][3]);
            acc[1][0] = fmaf(w1, x4.x, acc[1][0]); acc[1][1] = fmaf(w1, x4.y, acc[1][1]);
            acc[1][2] = fmaf(w1, x4.z, acc[1][2]); acc[1][3] = fmaf(w1, x4.w, acc[1][3]);
            acc[2][0] = fmaf(w2, x4.x, acc[2][0]); acc[2][1] = fmaf(w2, x4.y, acc[2][1]);
            acc[2][2] = fmaf(w2, x4.z, acc[2][2]); acc[2][3] = fmaf(w2, x4.w, acc[2][3]);
            acc[3][0] = fmaf(w3, x4.x, acc[3][0]); acc[3][1] = fmaf(w3, x4.y, acc[3][1]);
            acc[3][2] = fmaf(w3, x4.z, acc[3][2]); acc[3][3] = fmaf(w3, x4.w, acc[3][3]);
        }
    }
    float b0 = sb[d0], b1 = sb[d0+1], b2 = sb[d0+2], b3 = sb[d0+3];
    #pragma unroll
    for (int j = 0; j < 4; j++) {
        int n = nblk + n0 + j;
        float4 o = make_float4(acc[0][j]+b0, acc[1][j]+b1, acc[2][j]+b2, acc[3][j]+b3);
        *(float4*)&out[((size_t)b*Nc + n)*Dc + d0] = o;
    }
}

// ---------------- KNN ------------------------------------------------------
__global__ void knn_kernel(const float* __restrict__ pq, const float* __restrict__ ps) {
    __shared__ float4 sp[Mc];   // 32 KB
    int b = blockIdx.y;
    const float* p = ps + (size_t)b*3*Mc;
    for (int i = threadIdx.x; i < Mc; i += 64) {
        float x = p[i], y = p[Mc + i], z = p[2*Mc + i];
        sp[i] = make_float4(x, y, z, x*x + y*y + z*z);
    }
    __syncthreads();
    int n = blockIdx.x * 64 + threadIdx.x;
    const float* pqb = pq + (size_t)b*3*Nc;
    float qx = pqb[n], qy = pqb[Nc + n], qz = pqb[2*Nc + n];
    float qq = qx*qx + qy*qy + qz*qz;
    float bd[Kc]; int bi[Kc];
    #pragma unroll
    for (int j = 0; j < Kc; j++) { bd[j] = 3.4e38f; bi[j] = 0; }
    float worst = 3.4e38f; int wpos = 0;
    for (int m = 0; m < Mc; m++) {
        float4 c = sp[m];
        float dot = qx*c.x + qy*c.y + qz*c.z;
        float d2 = qq + c.w - 2.0f*dot;
        if (d2 < worst) {
            #pragma unroll
            for (int j = 0; j < Kc; j++) if (j == wpos) { bd[j] = d2; bi[j] = m; }
            worst = -3.4e38f;
            #pragma unroll
            for (int j = 0; j < Kc; j++) if (bd[j] > worst) { worst = bd[j]; wpos = j; }
        }
    }
    int* o = g_idx + ((size_t)b*Nc + n)*Kc;
    #pragma unroll
    for (int j = 0; j < Kc; j++) o[j] = bi[j];
}

// ---------------- pe1 = Wp1 @ pos_rel + bp1 --------------------------------
__global__ void pe1_kernel(const float* __restrict__ pq, const float* __restrict__ ps,
                           const float* __restrict__ Wp1, const float* __restrict__ bp1) {
    __shared__ float srel[64][3];
    int p0 = blockIdx.x * 64;
    int t = threadIdx.x;
    if (t < 64) {
        int p = p0 + t;
        int b = p >> 15;
        int rem = p & 32767;
        int n = rem >> 4;
        int iv = g_idx[p];
        const float* pqb = pq + (size_t)b*3*Nc;
        const float* psb = ps + (size_t)b*3*Mc;
        srel[t][0] = pqb[n]        - psb[iv];
        srel[t][1] = pqb[Nc + n]   - psb[Mc + iv];
        srel[t][2] = pqb[2*Nc + n] - psb[2*Mc + iv];
    }
    __syncthreads();
    int d = t & 63, slot = t >> 6;
    float w0 = Wp1[d*3], w1 = Wp1[d*3+1], w2 = Wp1[d*3+2], bb = bp1[d];
    for (int i = slot; i < 64; i += 4) {
        float x = fmaf(w0, srel[i][0], fmaf(w1, srel[i][1], fmaf(w2, srel[i][2], bb)));
        g_pe[(size_t)(p0 + i)*Dc + d] = x;
    }
}

// ---------------- BN1 stats over g_pe ---------------------------------------
__global__ void stats_pe_kernel() {
    int ch  = threadIdx.x & 63;
    long r0 = (long)blockIdx.x*4 + (threadIdx.x >> 6);
    float s = 0.f, s2 = 0.f;
    for (long p = r0; p < NPTS; p += (long)gridDim.x*4) {
        float x = g_pe[p*Dc + ch];
        s += x; s2 += x*x;
    }
    atomicAdd(&g_sum1[ch], (double)s);
    atomicAdd(&g_sq1[ch],  (double)s2);
}

__global__ void finalize_kernel(int which) {
    int c = threadIdx.x;
    const double inv = 1.0 / (double)NPTS;
    if (which == 0) {
        if (c < Dc) {
            double m = g_sum1[c]*inv;
            double v = g_sq1[c]*inv - m*m;
            g_mean1[c] = (float)m;
            g_rstd1[c] = rsqrtf((float)v + EPSf);
        }
    } else {
        if (c < Hc) {
            double m = g_sum2[c]*inv;
            double v = g_sq2[c]*inv - m*m;
            g_mean2[c] = (float)m;
            g_rstd2[c] = rsqrtf((float)v + EPSf);
        }
    }
}

// ---------------- pe = Wp2 @ relu(BN1(pe1)) + bp2 ; a1 = Wa1 @ (q-k+pe) + ba1
// Block: 128 points. Stage1: 64x128 GEMM (4x4 tiles). Stage2: 256x128 GEMM (8x8 tiles).
// Also accumulates BN2 stats for a1 and writes g_a1 transposed [h][pt].
__global__ __launch_bounds__(512, 1)
void pe2_a1_kernel(const float* __restrict__ Wp2, const float* __restrict__ bp2,
                   const float* __restrict__ gp,  const float* __restrict__ btp,
                   const float* __restrict__ Wa1, const float* __restrict__ ba1) {
    extern __shared__ float sm6[];
    float* sWp2 = sm6;                 // [64 d][64 e] natural
    float* sWa1 = sWp2 + Dc*Dc;        // [256 h][64 e] natural
    float* sX   = sWa1 + Hc*Dc;        // [64 e][128 pt]  (Xr, then S)
    float* sbn  = sX + Dc*128;         // 64
    float* ssh  = sbn + Dc;            // 64
    float* sbp2 = ssh + Dc;            // 64
    float* sba1 = sbp2 + Dc;           // 256
    int t = threadIdx.x;
    for (int i = t; i < Dc*Dc; i += 512) sWp2[i] = Wp2[i];
    for (int i = t; i < Hc*Dc; i += 512) sWa1[i] = Wa1[i];
    if (t < Dc) {
        float sc = gp[t] * g_rstd1[t];
        sbn[t] = sc;
        ssh[t] = btp[t] - g_mean1[t]*sc;
        sbp2[t] = bp2[t];
    }
    if (t < Hc) sba1[t] = ba1[t];
    int p0 = blockIdx.x * 128;
    __syncthreads();
    // load pe1 tile transposed, apply BN1+relu
    for (int f = t; f < 2048; f += 512) {
        int d4 = f >> 7, ptl = f & 127;
        float4 v = *(const float4*)&g_pe[(size_t)(p0 + ptl)*Dc + d4*4];
        int d = d4*4;
        sX[(d+0)*128 + ptl] = fmaxf(fmaf(v.x, sbn[d+0], ssh[d+0]), 0.f);
        sX[(d+1)*128 + ptl] = fmaxf(fmaf(v.y, sbn[d+1], ssh[d+1]), 0.f);
        sX[(d+2)*128 + ptl] = fmaxf(fmaf(v.z, sbn[d+2], ssh[d+2]), 0.f);
        sX[(d+3)*128 + ptl] = fmaxf(fmaf(v.w, sbn[d+3], ssh[d+3]), 0.f);
    }
    __syncthreads();
    // -------- Stage 1 GEMM: pe = Wp2 @ Xr --------
    int og2 = t >> 5, pg2 = t & 31;
    int d0 = og2*4, pt0 = pg2*4;
    float acc[4][4];
    #pragma unroll
    for (int q = 0; q < 4; q++)
        #pragma unroll
        for (int j = 0; j < 4; j++) acc[q][j] = 0.f;
    #pragma unroll 4
    for (int e = 0; e < Dc; e++) {
        float4 x4 = *(const float4*)&sX[e*128 + pt0];
        float w0 = sWp2[(d0+0)*Dc + e];
        float w1 = sWp2[(d0+1)*Dc + e];
        float w2 = sWp2[(d0+2)*Dc + e];
        float w3 = sWp2[(d0+3)*Dc + e];
        acc[0][0] = fmaf(w0, x4.x, acc[0][0]); acc[0][1] = fmaf(w0, x4.y, acc[0][1]);
        acc[0][2] = fmaf(w0, x4.z, acc[0][2]); acc[0][3] = fmaf(w0, x4.w, acc[0][3]);
        acc[1][0] = fmaf(w1, x4.x, acc[1][0]); acc[1][1] = fmaf(w1, x4.y, acc[1][1]);
        acc[1][2] = fmaf(w1, x4.z, acc[1][2]); acc[1][3] = fmaf(w1, x4.w, acc[1][3]);
        acc[2][0] = fmaf(w2, x4.x, acc[2][0]); acc[2][1] = fmaf(w2, x4.y, acc[2][1]);
        acc[2][2] = fmaf(w2, x4.z, acc[2][2]); acc[2][3] = fmaf(w2, x4.w, acc[2][3]);
        acc[3][0] = fmaf(w3, x4.x, acc[3][0]); acc[3][1] = fmaf(w3, x4.y, acc[3][1]);
        acc[3][2] = fmaf(w3, x4.z, acc[3][2]); acc[3][3] = fmaf(w3, x4.w, acc[3][3]);
    }
    __syncthreads();   // all reads of sX(Xr) done; safe to overwrite with S
    // epilogue 1: write pe to gmem; S = pe + q - k into sX
    float bb0 = sbp2[d0], bb1 = sbp2[d0+1], bb2 = sbp2[d0+2], bb3 = sbp2[d0+3];
    #pragma unroll
    for (int j = 0; j < 4; j++) {
        int pt = p0 + pt0 + j;
        int b  = pt >> 15;
        int n  = (pt & 32767) >> 4;
        int iv = g_idx[pt];
        float4 q4 = *(const float4*)&g_q[((size_t)b*Nc + n)*Dc + d0];
        float4 k4 = *(const float4*)&g_k[((size_t)b*Mc + iv)*Dc + d0];
        float4 pe4 = make_float4(acc[0][j]+bb0, acc[1][j]+bb1, acc[2][j]+bb2, acc[3][j]+bb3);
        *(float4*)&g_pe[(size_t)pt*Dc + d0] = pe4;
        sX[(d0+0)*128 + pt0 + j] = pe4.x + q4.x - k4.x;
        sX[(d0+1)*128 + pt0 + j] = pe4.y + q4.y - k4.y;
        sX[(d0+2)*128 + pt0 + j] = pe4.z + q4.z - k4.z;
        sX[(d0+3)*128 + pt0 + j] = pe4.w + q4.w - k4.w;
    }
    __syncthreads();
    // -------- Stage 2 GEMM: a1 = Wa1 @ S (8x8 thread tiles) --------
    int og = t >> 4, pg = t & 15;
    int h0 = og*8, q0 = pg*8;
    float a[8][8];
    #pragma unroll
    for (int hh = 0; hh < 8; hh++)
        #pragma unroll
        for (int j = 0; j < 8; j++) a[hh][j] = 0.f;
    for (int e = 0; e < Dc; e++) {
        float4 xa = *(const float4*)&sX[e*128 + q0];
        float4 xb = *(const float4*)&sX[e*128 + q0 + 4];
        float xs[8] = {xa.x, xa.y, xa.z, xa.w, xb.x, xb.y, xb.z, xb.w};
        #pragma unroll
        for (int hh = 0; hh < 8; hh++) {
            float w = sWa1[(h0+hh)*Dc + e];
            #pragma unroll
            for (int j = 0; j < 8; j++)
                a[hh][j] = fmaf(w, xs[j], a[hh][j]);
        }
    }
    // epilogue 2: bias, store g_a1[h][pt], BN2 stats
    #pragma unroll
    for (int hh = 0; hh < 8; hh++) {
        int h = h0 + hh;
        float bias = sba1[h];
        float s = 0.f, s2 = 0.f;
        float vv[8];
        #pragma unroll
        for (int j = 0; j < 8; j++) {
            float v = a[hh][j] + bias;
            vv[j] = v;
            s += v; s2 += v*v;
        }
        float* op = &g_a1[(size_t)h*NPTS + p0 + q0];
        *(float4*)op       = make_float4(vv[0], vv[1], vv[2], vv[3]);
        *(float4*)(op + 4) = make_float4(vv[4], vv[5], vv[6], vv[7]);
        #pragma unroll
        for (int off = 8; off > 0; off >>= 1) {
            s  += __shfl_xor_sync(0xffffffffu, s, off);
            s2 += __shfl_xor_sync(0xffffffffu, s2, off);
        }
        if (pg == 0) {
            atomicAdd(&g_sum2[h], (double)s);
            atomicAdd(&g_sq2[h],  (double)s2);
        }
    }
}

// ---------------- a2 = Wa2 @ relu(BN2(a1)) + ba2 ; softmax over K; aggregate
// Block: 128 points = 8 n x 16 k. Output tile 64 d x 128 pt (4x4 thread tiles).
__global__ __launch_bounds__(512, 2)
void a2_softagg_kernel(const float* __restrict__ Wa2, const float* __restrict__ ba2,
                       const float* __restrict__ ga,  const float* __restrict__ bta) {
    extern __shared__ float sm7[];
    float* sW   = sm7;             // [64 d][64 hl] natural slice
    float* sA   = sW + Dc*64;      // [64 hl][128 pt]; later sOut [128 pt][65]
    float* ssc  = sA + 8320;       // 256
    float* ssh2 = ssc + Hc;        // 256
    float* sba2 = ssh2 + Hc;       // 64
    int t = threadIdx.x;
    int p0 = blockIdx.x * 128;
    int b  = p0 >> 15;
    if (t < Hc) {
        float sc = ga[t] * g_rstd2[t];
        ssc[t] = sc;
        ssh2[t] = bta[t] - g_mean2[t]*sc;
    }
    if (t < Dc) sba2[t] = ba2[t];
    int og3 = t >> 5, pg3 = t & 31;
    int d0 = og3*4, pt0 = pg3*4;
    float acc[4][4];
    #pragma unroll
    for (int q = 0; q < 4; q++)
        #pragma unroll
        for (int j = 0; j < 4; j++) acc[q][j] = 0.f;
    for (int ks = 0; ks < 4; ks++) {
        int h0k = ks*64;
        __syncthreads();
        for (int i = t; i < Dc*64; i += 512) {
            int d = i >> 6, hl = i & 63;
            sW[d*64 + hl] = Wa2[(size_t)d*Hc + h0k + hl];
        }
        for (int f = t; f < 2048; f += 512) {
            int hl = f >> 5, pt4 = f & 31;
            int h = h0k + hl;
            float4 v = *(const float4*)&g_a1[(size_t)h*NPTS + p0 + pt4*4];
            float sc = ssc[h], sh = ssh2[h];
            float4 o = make_float4(fmaxf(fmaf(v.x, sc, sh), 0.f),
                                   fmaxf(fmaf(v.y, sc, sh), 0.f),
                                   fmaxf(fmaf(v.z, sc, sh), 0.f),
                                   fmaxf(fmaf(v.w, sc, sh), 0.f));
            *(float4*)&sA[hl*128 + pt4*4] = o;
        }
        __syncthreads();
        #pragma unroll 4
        for (int hl = 0; hl < 64; hl++) {
            float4 x4 = *(const float4*)&sA[hl*128 + pt0];
            float w0 = sW[(d0+0)*64 + hl];
            float w1 = sW[(d0+1)*64 + hl];
            float w2 = sW[(d0+2)*64 + hl];
            float w3 = sW[(d0+3)*64 + hl];
            acc[0][0] = fmaf(w0, x4.x, acc[0][0]); acc[0][1] = fmaf(w0, x4.y, acc[0][1]);
            acc[0][2] = fmaf(w0, x4.z, acc[0][2]); acc[0][3] = fmaf(w0, x4.w, acc[0][3]);
            acc[1][0] = fmaf(w1, x4.x, acc[1][0]); acc[1][1] = fmaf(w1, x4.y, acc[1][1]);
            acc[1][2] = fmaf(w1, x4.z, acc[1][2]); acc[1][3] = fmaf(w1, x4.w, acc[1][3]);
            acc[2][0] = fmaf(w2, x4.x, acc[2][0]); acc[2][1] = fmaf(w2, x4.y, acc[2][1]);
            acc[2][2] = fmaf(w2, x4.z, acc[2][2]); acc[2][3] = fmaf(w2, x4.w, acc[2][3]);
            acc[3][0] = fmaf(w3, x4.x, acc[3][0]); acc[3][1] = fmaf(w3, x4.y, acc[3][1]);
            acc[3][2] = fmaf(w3, x4.z, acc[3][2]); acc[3][3] = fmaf(w3, x4.w, acc[3][3]);
        }
    }
    __syncthreads();
    // write a2 tile transposed to smem [pt][65]
    float* sOut = sA;
    #pragma unroll
    for (int j = 0; j < 4; j++) {
        int pt = pt0 + j;
        sOut[pt*65 + d0+0] = acc[0][j] + sba2[d0+0];
        sOut[pt*65 + d0+1] = acc[1][j] + sba2[d0+1];
        sOut[pt*65 + d0+2] = acc[2][j] + sba2[d0+2];
        sOut[pt*65 + d0+3] = acc[3][j] + sba2[d0+3];
    }
    __syncthreads();
    // softmax over 16 neighbors + aggregate; thread = (nl, d)
    int d  = t & 63;
    int nl = t >> 6;
    int base = nl*16;
    float av[Kc];
    float mx = -3.4e38f;
    #pragma unroll
    for (int k = 0; k < Kc; k++) {
        av[k] = sOut[(base + k)*65 + d];
        mx = fmaxf(mx, av[k]);
    }
    float sum = 0.f;
    #pragma unroll
    for (int k = 0; k < Kc; k++) { av[k] = __expf(av[k] - mx); sum += av[k]; }
    float inv = 1.f / sum;
    const int* ip = g_idx + p0 + base;
    float agg = 0.f;
    #pragma unroll
    for (int k = 0; k < Kc; k++) {
        int iv = ip[k];
        float vg = g_v[((size_t)b*Mc + iv)*Dc + d];
        float pe = g_pe[(size_t)(p0 + base + k)*Dc + d];
        agg = fmaf(av[k]*inv, vg + pe, agg);
    }
    int bn = (p0 >> 4) + nl;
    g_agg[(size_t)bn*Dc + d] = agg;
}

// ---------------- out = We @ agg + be + fq ---------------------------------
__global__ __launch_bounds__(512, 2)
void final_kernel(const float* __restrict__ We, const float* __restrict__ be,
                  const float* __restrict__ fq, float* __restrict__ out) {
    extern __shared__ float sm8[];
    float* sWe = sm8;              // [128 c][64 d] natural
    float* sG  = sWe + Cc*Dc;      // [64 d][128 n]
    float* sbe = sG + Dc*128;      // 128
    int t = threadIdx.x;
    int b = blockIdx.y;
    int nblk = blockIdx.x * 128;
    for (int i = t; i < Cc*Dc; i += 512) sWe[i] = We[i];
    if (t < Cc) sbe[t] = be[t];
    for (int f = t; f < 2048; f += 512) {
        int d4 = f >> 7, nl = f & 127;
        float4 v = *(const float4*)&g_agg[((size_t)b*Nc + nblk + nl)*Dc + d4*4];
        int d = d4*4;
        sG[(d+0)*128 + nl] = v.x;
        sG[(d+1)*128 + nl] = v.y;
        sG[(d+2)*128 + nl] = v.z;
        sG[(d+3)*128 + nl] = v.w;
    }
    __syncthreads();
    int og = t >> 4, pg = t & 15;
    int c0 = og*4, n0 = pg*8;
    float acc[4][8];
    #pragma unroll
    for (int q = 0; q < 4; q++)
        #pragma unroll
        for (int j = 0; j < 8; j++) acc[q][j] = 0.f;
    for (int e = 0; e < Dc; e++) {
        float4 xa = *(const float4*)&sG[e*128 + n0];
        float4 xb = *(const float4*)&sG[e*128 + n0 + 4];
        float xs[8] = {xa.x, xa.y, xa.z, xa.w, xb.x, xb.y, xb.z, xb.w};
        #pragma unroll
        for (int q = 0; q < 4; q++) {
            float w = sWe[(c0+q)*Dc + e];
            #pragma unroll
            for (int j = 0; j < 8; j++)
                acc[q][j] = fmaf(w, xs[j], acc[q][j]);
        }
    }
    #pragma unroll
    for (int q = 0; q < 4; q++) {
        int c = c0 + q;
        float bc = sbe[c];
        size_t o = (size_t)b*Cc*Nc + (size_t)c*Nc + nblk + n0;
        float4 f0 = *(const float4*)&fq[o];
        float4 f1 = *(const float4*)&fq[o + 4];
        *(float4*)&out[o]     = make_float4(acc[q][0]+bc+f0.x, acc[q][1]+bc+f0.y,
                                            acc[q][2]+bc+f0.z, acc[q][3]+bc+f0.w);
        *(float4*)&out[o + 4] = make_float4(acc[q][4]+bc+f1.x, acc[q][5]+bc+f1.y,
                                            acc[q][6]+bc+f1.z, acc[q][7]+bc+f1.w);
    }
}

// ---------------- launch -----------------------------------------------------
extern "C" void kernel_launch(void* const* d_in, const int* in_sizes, int n_in,
                              void* d_out, int out_size) {
    const float* pq  = (const float*)d_in[0];
    const float* fq  = (const float*)d_in[1];
    const float* ps  = (const float*)d_in[2];
    const float* fs  = (const float*)d_in[3];
    const float* Wq  = (const float*)d_in[4];  const float* bq  = (const float*)d_in[5];
    const float* Wk  = (const float*)d_in[6];  const float* bk  = (const float*)d_in[7];
    const float* Wv  = (const float*)d_in[8];  const float* bv  = (const float*)d_in[9];
    const float* Wp1 = (const float*)d_in[10]; const float* bp1 = (const float*)d_in[11];
    const float* gp  = (const float*)d_in[12]; const float* btp = (const float*)d_in[13];
    const float* Wp2 = (const float*)d_in[14]; const float* bp2 = (const float*)d_in[15];
    const float* Wa1 = (const float*)d_in[16]; const float* ba1 = (const float*)d_in[17];
    const float* ga  = (const float*)d_in[18]; const float* bta = (const float*)d_in[19];
    const float* Wa2 = (const float*)d_in[20]; const float* ba2 = (const float*)d_in[21];
    const float* We  = (const float*)d_in[22]; const float* be  = (const float*)d_in[23];
    float* out = (float*)d_out;

    const int SMEM_QKV = (Dc*Cc + 32*128 + Dc) * (int)sizeof(float);
    const int SMEM_PA  = (Dc*Dc + Hc*Dc + Dc*128 + 3*Dc + Hc) * (int)sizeof(float);
    const int SMEM_A2  = (Dc*64 + 8320 + 2*Hc + Dc) * (int)sizeof(float);
    const int SMEM_FIN = (Cc*Dc + Dc*128 + Cc) * (int)sizeof(float);
    cudaFuncSetAttribute(qkv_kernel,        cudaFuncAttributeMaxDynamicSharedMemorySize, SMEM_QKV);
    cudaFuncSetAttribute(pe2_a1_kernel,     cudaFuncAttributeMaxDynamicSharedMemorySize, SMEM_PA);
    cudaFuncSetAttribute(a2_softagg_kernel, cudaFuncAttributeMaxDynamicSharedMemorySize, SMEM_A2);
    cudaFuncSetAttribute(final_kernel,      cudaFuncAttributeMaxDynamicSharedMemorySize, SMEM_FIN);

    zero_stats_kernel<<<1, 256>>>();
    qkv_kernel<<<dim3(Nc/128, 12), 512, SMEM_QKV>>>(fq, fs, Wq, bq, Wk, bk, Wv, bv);
    knn_kernel<<<dim3(Nc/64, Bc), 64>>>(pq, ps);
    pe1_kernel<<<NPTS/64, 256>>>(pq, ps, Wp1, bp1);
    stats_pe_kernel<<<128, 256>>>();
    finalize_kernel<<<1, 256>>>(0);
    pe2_a1_kernel<<<NPTS/128, 512, SMEM_PA>>>(Wp2, bp2, gp, btp, Wa1, ba1);
    finalize_kernel<<<1, 256>>>(1);
    a2_softagg_kernel<<<NPTS/128, 512, SMEM_A2>>>(Wa2, ba2, ga, bta);
    final_kernel<<<dim3(Nc/128, Bc), 512, SMEM_FIN>>>(We, be, fq, out);
}

// round 4
// speedup vs baseline: 1.7146x; 1.0820x over previous
#include <cuda_runtime.h>
#include <math.h>

#define Bc 4
#define Cc 128
#define Dc 64
#define Nc 2048
#define Mc 2048
#define Hc 256
#define Kc 16
#define NPTS (Bc*Nc*Kc)   // 131072
#define EPSf 1e-5f

typedef unsigned long long u64;

__device__ __forceinline__ u64 pack2(float lo, float hi) {
    u64 r; asm("mov.b64 %0, {%1,%2};" : "=l"(r) : "f"(lo), "f"(hi)); return r;
}
__device__ __forceinline__ float2 unpack2(u64 v) {
    float2 r; asm("mov.b64 {%0,%1}, %2;" : "=f"(r.x), "=f"(r.y) : "l"(v)); return r;
}
__device__ __forceinline__ u64 fma2(u64 a, u64 b, u64 c) {
    u64 d; asm("fma.rn.f32x2 %0, %1, %2, %3;" : "=l"(d) : "l"(a), "l"(b), "l"(c)); return d;
}

// ---------------- scratch (static device globals; allocation-free) ----------
__device__ __align__(256) float g_q[Bc*Nc*Dc];
__device__ __align__(256) float g_k[Bc*Mc*Dc];
__device__ __align__(256) float g_v[Bc*Mc*Dc];
__device__ __align__(256) int   g_idx[NPTS];
__device__ __align__(256) float g_pe[NPTS*Dc];            // pe1 then pe (in place)
__device__ __align__(256) float g_a1[(size_t)NPTS*Hc];    // 134 MB, layout [h][pt]
__device__ __align__(256) float g_agg[Bc*Nc*Dc];
__device__ double g_sum1[Dc], g_sq1[Dc];
__device__ double g_sum2[Hc], g_sq2[Hc];
__device__ float g_mean1[Dc], g_rstd1[Dc];
__device__ float g_mean2[Hc], g_rstd2[Hc];

// ---------------- zero stats ------------------------------------------------
__global__ void zero_stats_kernel() {
    int t = threadIdx.x;
    if (t < Dc) { g_sum1[t] = 0.0; g_sq1[t] = 0.0; }
    if (t < Hc) { g_sum2[t] = 0.0; g_sq2[t] = 0.0; }
}

// ---------------- q/k/v 1x1 convs as tiled GEMM ----------------------------
__global__ __launch_bounds__(512, 2)
void qkv_kernel(const float* __restrict__ fq, const float* __restrict__ fs,
                const float* __restrict__ Wq, const float* __restrict__ bq,
                const float* __restrict__ Wk, const float* __restrict__ bk,
                const float* __restrict__ Wv, const float* __restrict__ bv) {
    extern __shared__ float sm0[];
    float* sW = sm0;            // [64 d][128 c] natural
    float* sF = sW + Dc*Cc;     // [32 c][128 n] stage
    float* sb = sF + 32*128;    // 64
    int zw = blockIdx.y;
    int which = zw >> 2, b = zw & 3;
    const float* f    = (which == 0) ? fq : fs;
    const float* W    = (which == 0) ? Wq : (which == 1 ? Wk : Wv);
    const float* bias = (which == 0) ? bq : (which == 1 ? bk : bv);
    float* out        = (which == 0) ? g_q : (which == 1 ? g_k : g_v);
    int t = threadIdx.x;
    for (int i = t; i < Dc*Cc; i += 512) sW[i] = W[i];
    if (t < Dc) sb[t] = bias[t];
    int nblk = blockIdx.x * 128;
    const float* fb = f + (size_t)b*Cc*Nc + nblk;
    int og = t >> 5, pg = t & 31;
    int d0 = og*4, n0 = pg*4;
    u64 acc[4][2];
    #pragma unroll
    for (int q = 0; q < 4; q++) { acc[q][0] = 0ull; acc[q][1] = 0ull; }
    for (int ks = 0; ks < 4; ks++) {
        int c0 = ks*32;
        __syncthreads();
        for (int i = t; i < 32*128; i += 512) {
            int cl = i >> 7, nl = i & 127;
            sF[cl*128 + nl] = fb[(size_t)(c0 + cl)*Nc + nl];
        }
        __syncthreads();
        #pragma unroll 4
        for (int cl = 0; cl < 32; cl++) {
            ulonglong2 x2 = *(const ulonglong2*)&sF[cl*128 + n0];
            #pragma unroll
            for (int q = 0; q < 4; q++) {
                float w = sW[(d0+q)*Cc + c0 + cl];
                u64 wp = pack2(w, w);
                acc[q][0] = fma2(wp, x2.x, acc[q][0]);
                acc[q][1] = fma2(wp, x2.y, acc[q][1]);
            }
        }
    }
    float b0 = sb[d0], b1 = sb[d0+1], b2 = sb[d0+2], b3 = sb[d0+3];
    float2 a0l = unpack2(acc[0][0]), a0h = unpack2(acc[0][1]);
    float2 a1l = unpack2(acc[1][0]), a1h = unpack2(acc[1][1]);
    float2 a2l = unpack2(acc[2][0]), a2h = unpack2(acc[2][1]);
    float2 a3l = unpack2(acc[3][0]), a3h = unpack2(acc[3][1]);
    float vx[4][4] = {{a0l.x,a0l.y,a0h.x,a0h.y},{a1l.x,a1l.y,a1h.x,a1h.y},
                      {a2l.x,a2l.y,a2h.x,a2h.y},{a3l.x,a3l.y,a3h.x,a3h.y}};
    #pragma unroll
    for (int j = 0; j < 4; j++) {
        int n = nblk + n0 + j;
        float4 o = make_float4(vx[0][j]+b0, vx[1][j]+b1, vx[2][j]+b2, vx[3][j]+b3);
        *(float4*)&out[((size_t)b*Nc + n)*Dc + d0] = o;
    }
}

// ---------------- KNN ------------------------------------------------------
__global__ void knn_kernel(const float* __restrict__ pq, const float* __restrict__ ps) {
    __shared__ float4 sp[Mc];   // 32 KB
    int b = blockIdx.y;
    const float* p = ps + (size_t)b*3*Mc;
    for (int i = threadIdx.x; i < Mc; i += 64) {
        float x = p[i], y = p[Mc + i], z = p[2*Mc + i];
        sp[i] = make_float4(x, y, z, x*x + y*y + z*z);
    }
    __syncthreads();
    int n = blockIdx.x * 64 + threadIdx.x;
    const float* pqb = pq + (size_t)b*3*Nc;
    float qx = pqb[n], qy = pqb[Nc + n], qz = pqb[2*Nc + n];
    float qq = qx*qx + qy*qy + qz*qz;
    float bd[Kc]; int bi[Kc];
    #pragma unroll
    for (int j = 0; j < Kc; j++) { bd[j] = 3.4e38f; bi[j] = 0; }
    float worst = 3.4e38f; int wpos = 0;
    for (int m = 0; m < Mc; m++) {
        float4 c = sp[m];
        float dot = qx*c.x + qy*c.y + qz*c.z;
        float d2 = qq + c.w - 2.0f*dot;
        if (d2 < worst) {
            #pragma unroll
            for (int j = 0; j < Kc; j++) if (j == wpos) { bd[j] = d2; bi[j] = m; }
            worst = -3.4e38f;
            #pragma unroll
            for (int j = 0; j < Kc; j++) if (bd[j] > worst) { worst = bd[j]; wpos = j; }
        }
    }
    int* o = g_idx + ((size_t)b*Nc + n)*Kc;
    #pragma unroll
    for (int j = 0; j < Kc; j++) o[j] = bi[j];
}

// ---------------- pe1 = Wp1 @ pos_rel + bp1 --------------------------------
__global__ void pe1_kernel(const float* __restrict__ pq, const float* __restrict__ ps,
                           const float* __restrict__ Wp1, const float* __restrict__ bp1) {
    __shared__ float srel[64][3];
    int p0 = blockIdx.x * 64;
    int t = threadIdx.x;
    if (t < 64) {
        int p = p0 + t;
        int b = p >> 15;
        int rem = p & 32767;
        int n = rem >> 4;
        int iv = g_idx[p];
        const float* pqb = pq + (size_t)b*3*Nc;
        const float* psb = ps + (size_t)b*3*Mc;
        srel[t][0] = pqb[n]        - psb[iv];
        srel[t][1] = pqb[Nc + n]   - psb[Mc + iv];
        srel[t][2] = pqb[2*Nc + n] - psb[2*Mc + iv];
    }
    __syncthreads();
    int d = t & 63, slot = t >> 6;
    float w0 = Wp1[d*3], w1 = Wp1[d*3+1], w2 = Wp1[d*3+2], bb = bp1[d];
    for (int i = slot; i < 64; i += 4) {
        float x = fmaf(w0, srel[i][0], fmaf(w1, srel[i][1], fmaf(w2, srel[i][2], bb)));
        g_pe[(size_t)(p0 + i)*Dc + d] = x;
    }
}

// ---------------- BN1 stats over g_pe ---------------------------------------
__global__ void stats_pe_kernel() {
    int ch  = threadIdx.x & 63;
    long r0 = (long)blockIdx.x*4 + (threadIdx.x >> 6);
    float s = 0.f, s2 = 0.f;
    for (long p = r0; p < NPTS; p += (long)gridDim.x*4) {
        float x = g_pe[p*Dc + ch];
        s += x; s2 += x*x;
    }
    atomicAdd(&g_sum1[ch], (double)s);
    atomicAdd(&g_sq1[ch],  (double)s2);
}

__global__ void finalize_kernel(int which) {
    int c = threadIdx.x;
    const double inv = 1.0 / (double)NPTS;
    if (which == 0) {
        if (c < Dc) {
            double m = g_sum1[c]*inv;
            double v = g_sq1[c]*inv - m*m;
            g_mean1[c] = (float)m;
            g_rstd1[c] = rsqrtf((float)v + EPSf);
        }
    } else {
        if (c < Hc) {
            double m = g_sum2[c]*inv;
            double v = g_sq2[c]*inv - m*m;
            g_mean2[c] = (float)m;
            g_rstd2[c] = rsqrtf((float)v + EPSf);
        }
    }
}

// ---------------- pe = Wp2 @ relu(BN1(pe1)) + bp2 ; a1 = Wa1 @ (q-k+pe) + ba1
__global__ __launch_bounds__(512, 1)
void pe2_a1_kernel(const float* __restrict__ Wp2, const float* __restrict__ bp2,
                   const float* __restrict__ gp,  const float* __restrict__ btp,
                   const float* __restrict__ Wa1, const float* __restrict__ ba1) {
    extern __shared__ float sm6[];
    float* sWp2 = sm6;                 // [64 d][64 e] natural
    float* sWa1 = sWp2 + Dc*Dc;        // [256 h][64 e] natural
    float* sX   = sWa1 + Hc*Dc;        // [64 e][128 pt]  (Xr, then S)
    float* sbn  = sX + Dc*128;         // 64
    float* ssh  = sbn + Dc;            // 64
    float* sbp2 = ssh + Dc;            // 64
    float* sba1 = sbp2 + Dc;           // 256
    int t = threadIdx.x;
    for (int i = t; i < Dc*Dc; i += 512) sWp2[i] = Wp2[i];
    for (int i = t; i < Hc*Dc; i += 512) sWa1[i] = Wa1[i];
    if (t < Dc) {
        float sc = gp[t] * g_rstd1[t];
        sbn[t] = sc;
        ssh[t] = btp[t] - g_mean1[t]*sc;
        sbp2[t] = bp2[t];
    }
    if (t < Hc) sba1[t] = ba1[t];
    int p0 = blockIdx.x * 128;
    __syncthreads();
    // load pe1 tile transposed, apply BN1+relu
    for (int f = t; f < 2048; f += 512) {
        int d4 = f >> 7, ptl = f & 127;
        float4 v = *(const float4*)&g_pe[(size_t)(p0 + ptl)*Dc + d4*4];
        int d = d4*4;
        sX[(d+0)*128 + ptl] = fmaxf(fmaf(v.x, sbn[d+0], ssh[d+0]), 0.f);
        sX[(d+1)*128 + ptl] = fmaxf(fmaf(v.y, sbn[d+1], ssh[d+1]), 0.f);
        sX[(d+2)*128 + ptl] = fmaxf(fmaf(v.z, sbn[d+2], ssh[d+2]), 0.f);
        sX[(d+3)*128 + ptl] = fmaxf(fmaf(v.w, sbn[d+3], ssh[d+3]), 0.f);
    }
    __syncthreads();
    // -------- Stage 1 GEMM: pe = Wp2 @ Xr (4d x 4pt, f32x2 paired on pt) ----
    int og2 = t >> 5, pg2 = t & 31;
    int d0 = og2*4, pt0 = pg2*4;
    u64 acc[4][2];
    #pragma unroll
    for (int q = 0; q < 4; q++) { acc[q][0] = 0ull; acc[q][1] = 0ull; }
    #pragma unroll 4
    for (int e = 0; e < Dc; e++) {
        ulonglong2 x2 = *(const ulonglong2*)&sX[e*128 + pt0];
        #pragma unroll
        for (int q = 0; q < 4; q++) {
            float w = sWp2[(d0+q)*Dc + e];
            u64 wp = pack2(w, w);
            acc[q][0] = fma2(wp, x2.x, acc[q][0]);
            acc[q][1] = fma2(wp, x2.y, acc[q][1]);
        }
    }
    __syncthreads();   // all reads of sX(Xr) done; safe to overwrite with S
    // epilogue 1: write pe to gmem; S = pe + q - k into sX
    {
        float bb[4] = {sbp2[d0], sbp2[d0+1], sbp2[d0+2], sbp2[d0+3]};
        float vx[4][4];
        #pragma unroll
        for (int q = 0; q < 4; q++) {
            float2 lo = unpack2(acc[q][0]), hi = unpack2(acc[q][1]);
            vx[q][0] = lo.x + bb[q]; vx[q][1] = lo.y + bb[q];
            vx[q][2] = hi.x + bb[q]; vx[q][3] = hi.y + bb[q];
        }
        #pragma unroll
        for (int j = 0; j < 4; j++) {
            int pt = p0 + pt0 + j;
            int b  = pt >> 15;
            int n  = (pt & 32767) >> 4;
            int iv = g_idx[pt];
            float4 q4 = *(const float4*)&g_q[((size_t)b*Nc + n)*Dc + d0];
            float4 k4 = *(const float4*)&g_k[((size_t)b*Mc + iv)*Dc + d0];
            float4 pe4 = make_float4(vx[0][j], vx[1][j], vx[2][j], vx[3][j]);
            *(float4*)&g_pe[(size_t)pt*Dc + d0] = pe4;
            sX[(d0+0)*128 + pt0 + j] = pe4.x + q4.x - k4.x;
            sX[(d0+1)*128 + pt0 + j] = pe4.y + q4.y - k4.y;
            sX[(d0+2)*128 + pt0 + j] = pe4.z + q4.z - k4.z;
            sX[(d0+3)*128 + pt0 + j] = pe4.w + q4.w - k4.w;
        }
    }
    __syncthreads();
    // -------- Stage 2 GEMM: a1 = Wa1 @ S (8h x 8pt, f32x2 paired on pt) ----
    int og = t >> 4, pg = t & 15;
    int h0 = og*8, q0 = pg*8;
    u64 a[8][4];
    #pragma unroll
    for (int hh = 0; hh < 8; hh++)
        #pragma unroll
        for (int j = 0; j < 4; j++) a[hh][j] = 0ull;
    for (int e = 0; e < Dc; e++) {
        ulonglong2 xa = *(const ulonglong2*)&sX[e*128 + q0];
        ulonglong2 xb = *(const ulonglong2*)&sX[e*128 + q0 + 4];
        #pragma unroll
        for (int hh = 0; hh < 8; hh++) {
            float w = sWa1[(h0+hh)*Dc + e];
            u64 wp = pack2(w, w);
            a[hh][0] = fma2(wp, xa.x, a[hh][0]);
            a[hh][1] = fma2(wp, xa.y, a[hh][1]);
            a[hh][2] = fma2(wp, xb.x, a[hh][2]);
            a[hh][3] = fma2(wp, xb.y, a[hh][3]);
        }
    }
    // epilogue 2: bias, store g_a1[h][pt], BN2 stats
    #pragma unroll
    for (int hh = 0; hh < 8; hh++) {
        int h = h0 + hh;
        float bias = sba1[h];
        float vv[8];
        #pragma unroll
        for (int j = 0; j < 4; j++) {
            float2 u = unpack2(a[hh][j]);
            vv[j*2+0] = u.x + bias;
            vv[j*2+1] = u.y + bias;
        }
        float s = 0.f, s2 = 0.f;
        #pragma unroll
        for (int j = 0; j < 8; j++) { s += vv[j]; s2 += vv[j]*vv[j]; }
        float* op = &g_a1[(size_t)h*NPTS + p0 + q0];
        *(float4*)op       = make_float4(vv[0], vv[1], vv[2], vv[3]);
        *(float4*)(op + 4) = make_float4(vv[4], vv[5], vv[6], vv[7]);
        #pragma unroll
        for (int off = 8; off > 0; off >>= 1) {
            s  += __shfl_xor_sync(0xffffffffu, s, off);
            s2 += __shfl_xor_sync(0xffffffffu, s2, off);
        }
        if (pg == 0) {
            atomicAdd(&g_sum2[h], (double)s);
            atomicAdd(&g_sq2[h],  (double)s2);
        }
    }
}

// ---------------- a2 = Wa2 @ relu(BN2(a1)) + ba2 ; softmax over K; aggregate
__global__ __launch_bounds__(512, 2)
void a2_softagg_kernel(const float* __restrict__ Wa2, const float* __restrict__ ba2,
                       const float* __restrict__ ga,  const float* __restrict__ bta) {
    extern __shared__ float sm7[];
    float* sW   = sm7;             // [64 d][64 hl] natural slice
    float* sA   = sW + Dc*64;      // [64 hl][128 pt]; later sOut [128 pt][65]
    float* ssc  = sA + 8320;       // 256
    float* ssh2 = ssc + Hc;        // 256
    float* sba2 = ssh2 + Hc;       // 64
    int t = threadIdx.x;
    int p0 = blockIdx.x * 128;
    int b  = p0 >> 15;
    if (t < Hc) {
        float sc = ga[t] * g_rstd2[t];
        ssc[t] = sc;
        ssh2[t] = bta[t] - g_mean2[t]*sc;
    }
    if (t < Dc) sba2[t] = ba2[t];
    int og3 = t >> 5, pg3 = t & 31;
    int d0 = og3*4, pt0 = pg3*4;
    u64 acc[4][2];
    #pragma unroll
    for (int q = 0; q < 4; q++) { acc[q][0] = 0ull; acc[q][1] = 0ull; }
    for (int ks = 0; ks < 4; ks++) {
        int h0k = ks*64;
        __syncthreads();
        for (int i = t; i < Dc*64; i += 512) {
            int d = i >> 6, hl = i & 63;
            sW[d*64 + hl] = Wa2[(size_t)d*Hc + h0k + hl];
        }
        for (int f = t; f < 2048; f += 512) {
            int hl = f >> 5, pt4 = f & 31;
            int h = h0k + hl;
            float4 v = *(const float4*)&g_a1[(size_t)h*NPTS + p0 + pt4*4];
            float sc = ssc[h], sh = ssh2[h];
            float4 o = make_float4(fmaxf(fmaf(v.x, sc, sh), 0.f),
                                   fmaxf(fmaf(v.y, sc, sh), 0.f),
                                   fmaxf(fmaf(v.z, sc, sh), 0.f),
                                   fmaxf(fmaf(v.w, sc, sh), 0.f));
            *(float4*)&sA[hl*128 + pt4*4] = o;
        }
        __syncthreads();
        #pragma unroll 4
        for (int hl = 0; hl < 64; hl++) {
            ulonglong2 x2 = *(const ulonglong2*)&sA[hl*128 + pt0];
            #pragma unroll
            for (int q = 0; q < 4; q++) {
                float w = sW[(d0+q)*64 + hl];
                u64 wp = pack2(w, w);
                acc[q][0] = fma2(wp, x2.x, acc[q][0]);
                acc[q][1] = fma2(wp, x2.y, acc[q][1]);
            }
        }
    }
    __syncthreads();
    // write a2 tile transposed to smem [pt][65]
    float* sOut = sA;
    {
        float vx[4][4];
        #pragma unroll
        for (int q = 0; q < 4; q++) {
            float2 lo = unpack2(acc[q][0]), hi = unpack2(acc[q][1]);
            float bb = sba2[d0+q];
            vx[q][0] = lo.x + bb; vx[q][1] = lo.y + bb;
            vx[q][2] = hi.x + bb; vx[q][3] = hi.y + bb;
        }
        #pragma unroll
        for (int j = 0; j < 4; j++) {
            int pt = pt0 + j;
            sOut[pt*65 + d0+0] = vx[0][j];
            sOut[pt*65 + d0+1] = vx[1][j];
            sOut[pt*65 + d0+2] = vx[2][j];
            sOut[pt*65 + d0+3] = vx[3][j];
        }
    }
    __syncthreads();
    // softmax over 16 neighbors + aggregate; thread = (nl, d)
    int d  = t & 63;
    int nl = t >> 6;
    int base = nl*16;
    float av[Kc];
    float mx = -3.4e38f;
    #pragma unroll
    for (int k = 0; k < Kc; k++) {
        av[k] = sOut[(base + k)*65 + d];
        mx = fmaxf(mx, av[k]);
    }
    float sum = 0.f;
    #pragma unroll
    for (int k = 0; k < Kc; k++) { av[k] = __expf(av[k] - mx); sum += av[k]; }
    float inv = 1.f / sum;
    const int* ip = g_idx + p0 + base;
    float agg = 0.f;
    #pragma unroll
    for (int k = 0; k < Kc; k++) {
        int iv = ip[k];
        float vg = g_v[((size_t)b*Mc + iv)*Dc + d];
        float pe = g_pe[(size_t)(p0 + base + k)*Dc + d];
        agg = fmaf(av[k]*inv, vg + pe, agg);
    }
    int bn = (p0 >> 4) + nl;
    g_agg[(size_t)bn*Dc + d] = agg;
}

// ---------------- out = We @ agg + be + fq ---------------------------------
__global__ __launch_bounds__(512, 2)
void final_kernel(const float* __restrict__ We, const float* __restrict__ be,
                  const float* __restrict__ fq, float* __restrict__ out) {
    extern __shared__ float sm8[];
    float* sWe = sm8;              // [128 c][64 d] natural
    float* sG  = sWe + Cc*Dc;      // [64 d][128 n]
    float* sbe = sG + Dc*128;      // 128
    int t = threadIdx.x;
    int b = blockIdx.y;
    int nblk = blockIdx.x * 128;
    for (int i = t; i < Cc*Dc; i += 512) sWe[i] = We[i];
    if (t < Cc) sbe[t] = be[t];
    for (int f = t; f < 2048; f += 512) {
        int d4 = f >> 7, nl = f & 127;
        float4 v = *(const float4*)&g_agg[((size_t)b*Nc + nblk + nl)*Dc + d4*4];
        int d = d4*4;
        sG[(d+0)*128 + nl] = v.x;
        sG[(d+1)*128 + nl] = v.y;
        sG[(d+2)*128 + nl] = v.z;
        sG[(d+3)*128 + nl] = v.w;
    }
    __syncthreads();
    int og = t >> 4, pg = t & 15;
    int c0 = og*4, n0 = pg*8;
    u64 acc[4][4];
    #pragma unroll
    for (int q = 0; q < 4; q++)
        #pragma unroll
        for (int j = 0; j < 4; j++) acc[q][j] = 0ull;
    for (int e = 0; e < Dc; e++) {
        ulonglong2 xa = *(const ulonglong2*)&sG[e*128 + n0];
        ulonglong2 xb = *(const ulonglong2*)&sG[e*128 + n0 + 4];
        #pragma unroll
        for (int q = 0; q < 4; q++) {
            float w = sWe[(c0+q)*Dc + e];
            u64 wp = pack2(w, w);
            acc[q][0] = fma2(wp, xa.x, acc[q][0]);
            acc[q][1] = fma2(wp, xa.y, acc[q][1]);
            acc[q][2] = fma2(wp, xb.x, acc[q][2]);
            acc[q][3] = fma2(wp, xb.y, acc[q][3]);
        }
    }
    #pragma unroll
    for (int q = 0; q < 4; q++) {
        int c = c0 + q;
        float bc = sbe[c];
        float vv[8];
        #pragma unroll
        for (int j = 0; j < 4; j++) {
            float2 u = unpack2(acc[q][j]);
            vv[j*2+0] = u.x; vv[j*2+1] = u.y;
        }
        size_t o = (size_t)b*Cc*Nc + (size_t)c*Nc + nblk + n0;
        float4 f0 = *(const float4*)&fq[o];
        float4 f1 = *(const float4*)&fq[o + 4];
        *(float4*)&out[o]     = make_float4(vv[0]+bc+f0.x, vv[1]+bc+f0.y,
                                            vv[2]+bc+f0.z, vv[3]+bc+f0.w);
        *(float4*)&out[o + 4] = make_float4(vv[4]+bc+f1.x, vv[5]+bc+f1.y,
                                            vv[6]+bc+f1.z, vv[7]+bc+f1.w);
    }
}

// ---------------- launch -----------------------------------------------------
extern "C" void kernel_launch(void* const* d_in, const int* in_sizes, int n_in,
                              void* d_out, int out_size) {
    const float* pq  = (const float*)d_in[0];
    const float* fq  = (const float*)d_in[1];
    const float* ps  = (const float*)d_in[2];
    const float* fs  = (const float*)d_in[3];
    const float* Wq  = (const float*)d_in[4];  const float* bq  = (const float*)d_in[5];
    const float* Wk  = (const float*)d_in[6];  const float* bk  = (const float*)d_in[7];
    const float* Wv  = (const float*)d_in[8];  const float* bv  = (const float*)d_in[9];
    const float* Wp1 = (const float*)d_in[10]; const float* bp1 = (const float*)d_in[11];
    const float* gp  = (const float*)d_in[12]; const float* btp = (const float*)d_in[13];
    const float* Wp2 = (const float*)d_in[14]; const float* bp2 = (const float*)d_in[15];
    const float* Wa1 = (const float*)d_in[16]; const float* ba1 = (const float*)d_in[17];
    const float* ga  = (const float*)d_in[18]; const float* bta = (const float*)d_in[19];
    const float* Wa2 = (const float*)d_in[20]; const float* ba2 = (const float*)d_in[21];
    const float* We  = (const float*)d_in[22]; const float* be  = (const float*)d_in[23];
    float* out = (float*)d_out;

    const int SMEM_QKV = (Dc*Cc + 32*128 + Dc) * (int)sizeof(float);
    const int SMEM_PA  = (Dc*Dc + Hc*Dc + Dc*128 + 3*Dc + Hc) * (int)sizeof(float);
    const int SMEM_A2  = (Dc*64 + 8320 + 2*Hc + Dc) * (int)sizeof(float);
    const int SMEM_FIN = (Cc*Dc + Dc*128 + Cc) * (int)sizeof(float);
    cudaFuncSetAttribute(qkv_kernel,        cudaFuncAttributeMaxDynamicSharedMemorySize, SMEM_QKV);
    cudaFuncSetAttribute(pe2_a1_kernel,     cudaFuncAttributeMaxDynamicSharedMemorySize, SMEM_PA);
    cudaFuncSetAttribute(a2_softagg_kernel, cudaFuncAttributeMaxDynamicSharedMemorySize, SMEM_A2);
    cudaFuncSetAttribute(final_kernel,      cudaFuncAttributeMaxDynamicSharedMemorySize, SMEM_FIN);

    zero_stats_kernel<<<1, 256>>>();
    qkv_kernel<<<dim3(Nc/128, 12), 512, SMEM_QKV>>>(fq, fs, Wq, bq, Wk, bk, Wv, bv);
    knn_kernel<<<dim3(Nc/64, Bc), 64>>>(pq, ps);
    pe1_kernel<<<NPTS/64, 256>>>(pq, ps, Wp1, bp1);
    stats_pe_kernel<<<128, 256>>>();
    finalize_kernel<<<1, 256>>>(0);
    pe2_a1_kernel<<<NPTS/128, 512, SMEM_PA>>>(Wp2, bp2, gp, btp, Wa1, ba1);
    finalize_kernel<<<1, 256>>>(1);
    a2_softagg_kernel<<<NPTS/128, 512, SMEM_A2>>>(Wa2, ba2, ga, bta);
    final_kernel<<<dim3(Nc/128, Bc), 512, SMEM_FIN>>>(We, be, fq, out);
}

// round 5
// speedup vs baseline: 2.1166x; 1.2344x over previous
#include <cuda_runtime.h>
#include <math.h>

#define Bc 4
#define Cc 128
#define Dc 64
#define Nc 2048
#define Mc 2048
#define Hc 256
#define Kc 16
#define NPTS (Bc*Nc*Kc)   // 131072
#define EPSf 1e-5f

typedef unsigned long long u64;

__device__ __forceinline__ u64 pack2(float lo, float hi) {
    u64 r; asm("mov.b64 %0, {%1,%2};" : "=l"(r) : "f"(lo), "f"(hi)); return r;
}
__device__ __forceinline__ float2 unpack2(u64 v) {
    float2 r; asm("mov.b64 {%0,%1}, %2;" : "=f"(r.x), "=f"(r.y) : "l"(v)); return r;
}
__device__ __forceinline__ u64 fma2(u64 a, u64 b, u64 c) {
    u64 d; asm("fma.rn.f32x2 %0, %1, %2, %3;" : "=l"(d) : "l"(a), "l"(b), "l"(c)); return d;
}

// ---------------- scratch -----------------------------------------------
__device__ __align__(256) float g_q[Bc*Nc*Dc];
__device__ __align__(256) float g_k[Bc*Mc*Dc];
__device__ __align__(256) float g_v[Bc*Mc*Dc];
__device__ __align__(256) int   g_idx[NPTS];
__device__ __align__(256) float g_pe[NPTS*Dc];
__device__ __align__(256) float g_a1[(size_t)NPTS*Hc];    // [h][pt]
__device__ __align__(256) float g_agg[Bc*Nc*Dc];
__device__ double g_sum1[Dc], g_sq1[Dc];
__device__ double g_sum2[Hc], g_sq2[Hc];

// ---------------- q/k/v 1x1 convs as tiled GEMM ----------------------------
__global__ __launch_bounds__(512, 2)
void qkv_kernel(const float* __restrict__ fq, const float* __restrict__ fs,
                const float* __restrict__ Wq, const float* __restrict__ bq,
                const float* __restrict__ Wk, const float* __restrict__ bk,
                const float* __restrict__ Wv, const float* __restrict__ bv) {
    extern __shared__ float sm0[];
    float* sW = sm0;            // [64 d][128 c]
    float* sF = sW + Dc*Cc;     // [32 c][128 n]
    float* sb = sF + 32*128;    // 64
    int zw = blockIdx.y;
    int which = zw >> 2, b = zw & 3;
    const float* f    = (which == 0) ? fq : fs;
    const float* W    = (which == 0) ? Wq : (which == 1 ? Wk : Wv);
    const float* bias = (which == 0) ? bq : (which == 1 ? bk : bv);
    float* out        = (which == 0) ? g_q : (which == 1 ? g_k : g_v);
    int t = threadIdx.x;
    for (int i = t; i < Dc*Cc/4; i += 512) ((float4*)sW)[i] = ((const float4*)W)[i];
    if (t < Dc) sb[t] = bias[t];
    int nblk = blockIdx.x * 128;
    const float* fb = f + (size_t)b*Cc*Nc + nblk;
    int og = t >> 5, pg = t & 31;
    int d0 = og*4, n0 = pg*4;
    u64 acc[4][2];
    #pragma unroll
    for (int q = 0; q < 4; q++) { acc[q][0] = 0ull; acc[q][1] = 0ull; }
    for (int ks = 0; ks < 4; ks++) {
        int c0 = ks*32;
        __syncthreads();
        for (int i = t; i < 1024; i += 512) {
            int cl = i >> 5, nl4 = (i & 31);
            ((float4*)sF)[cl*32 + nl4] = *(const float4*)&fb[(size_t)(c0 + cl)*Nc + nl4*4];
        }
        __syncthreads();
        #pragma unroll 4
        for (int cl = 0; cl < 32; cl++) {
            ulonglong2 x2 = *(const ulonglong2*)&sF[cl*128 + n0];
            #pragma unroll
            for (int q = 0; q < 4; q++) {
                float w = sW[(d0+q)*Cc + c0 + cl];
                u64 wp = pack2(w, w);
                acc[q][0] = fma2(wp, x2.x, acc[q][0]);
                acc[q][1] = fma2(wp, x2.y, acc[q][1]);
            }
        }
    }
    float b0 = sb[d0], b1 = sb[d0+1], b2 = sb[d0+2], b3 = sb[d0+3];
    float vx[4][4];
    #pragma unroll
    for (int q = 0; q < 4; q++) {
        float2 lo = unpack2(acc[q][0]), hi = unpack2(acc[q][1]);
        vx[q][0]=lo.x; vx[q][1]=lo.y; vx[q][2]=hi.x; vx[q][3]=hi.y;
    }
    #pragma unroll
    for (int j = 0; j < 4; j++) {
        int n = nblk + n0 + j;
        float4 o = make_float4(vx[0][j]+b0, vx[1][j]+b1, vx[2][j]+b2, vx[3][j]+b3);
        *(float4*)&out[((size_t)b*Nc + n)*Dc + d0] = o;
    }
}

// ---------------- KNN: 4 threads/query, chunked scan + merge ---------------
__global__ __launch_bounds__(256, 2)
void knn_kernel(const float* __restrict__ pq, const float* __restrict__ ps) {
    extern __shared__ float smk[];
    float4* sp = (float4*)smk;          // 2048 float4 = 32 KB
    float*  cd = smk + 2048*4;          // [64 q][65] *? -> [64][65] per chunk set: [64][4*16+1]
    int*    ci = (int*)(cd + 64*65);    // [64][65]
    int t = threadIdx.x;
    int b = blockIdx.y;
    // one-time zero of stats accumulators
    if (blockIdx.x == 0 && blockIdx.y == 0) {
        if (t < Dc) { g_sum1[t] = 0.0; g_sq1[t] = 0.0; }
        g_sum2[t] = 0.0; g_sq2[t] = 0.0;   // t < 256 == Hc
    }
    const float* p = ps + (size_t)b*3*Mc;
    for (int i = t; i < Mc; i += 256) {
        float x = p[i], y = p[Mc + i], z = p[2*Mc + i];
        sp[i] = make_float4(x, y, z, x*x + y*y + z*z);
    }
    __syncthreads();
    int qi = t & 63, chunk = t >> 6;
    int n = blockIdx.x * 64 + qi;
    const float* pqb = pq + (size_t)b*3*Nc;
    float qx = pqb[n], qy = pqb[Nc + n], qz = pqb[2*Nc + n];
    float qq = qx*qx + qy*qy + qz*qz;
    float bd[Kc]; int bi[Kc];
    #pragma unroll
    for (int j = 0; j < Kc; j++) { bd[j] = 3.4e38f; bi[j] = 0; }
    float worst = 3.4e38f; int wpos = 0;
    int m0 = chunk*512;
    #pragma unroll 2
    for (int mm = 0; mm < 512; mm++) {
        int m = m0 + mm;
        float4 c = sp[m];
        float dot = qx*c.x + qy*c.y + qz*c.z;
        float d2 = qq + c.w - 2.0f*dot;
        if (d2 < worst) {
            #pragma unroll
            for (int j = 0; j < Kc; j++) if (j == wpos) { bd[j] = d2; bi[j] = m; }
            worst = -3.4e38f;
            #pragma unroll
            for (int j = 0; j < Kc; j++) if (bd[j] > worst) { worst = bd[j]; wpos = j; }
        }
    }
    #pragma unroll
    for (int j = 0; j < Kc; j++) {
        cd[qi*65 + chunk*16 + j] = bd[j];
        ci[qi*65 + chunk*16 + j] = bi[j];
    }
    __syncthreads();
    if (t < 64) {
        float fd[Kc]; int fi[Kc];
        #pragma unroll
        for (int j = 0; j < Kc; j++) { fd[j] = 3.4e38f; fi[j] = 0; }
        float w2 = 3.4e38f; int wp2 = 0;
        for (int c = 0; c < 64; c++) {
            float d2 = cd[t*65 + c];
            int   iv = ci[t*65 + c];
            if (d2 < w2) {
                #pragma unroll
                for (int j = 0; j < Kc; j++) if (j == wp2) { fd[j] = d2; fi[j] = iv; }
                w2 = -3.4e38f;
                #pragma unroll
                for (int j = 0; j < Kc; j++) if (fd[j] > w2) { w2 = fd[j]; wp2 = j; }
            }
        }
        int nn = blockIdx.x * 64 + t;
        int* o = g_idx + ((size_t)b*Nc + nn)*Kc;
        #pragma unroll
        for (int j = 0; j < Kc; j++) o[j] = fi[j];
    }
}

// ---------------- pe1 = Wp1 @ pos_rel + bp1, fused BN1 stats ---------------
__global__ __launch_bounds__(256, 4)
void pe1_stats_kernel(const float* __restrict__ pq, const float* __restrict__ ps,
                      const float* __restrict__ Wp1, const float* __restrict__ bp1) {
    __shared__ float srel[256*3];
    __shared__ float ssum[4*64], ssq[4*64];
    int p0 = blockIdx.x * 256;
    int t = threadIdx.x;
    {
        int p = p0 + t;
        int b = p >> 15;
        int nq = (p & 32767) >> 4;
        int iv = g_idx[p];
        const float* pqb = pq + (size_t)b*3*Nc;
        const float* psb = ps + (size_t)b*3*Mc;
        srel[t*3+0] = pqb[nq]        - psb[iv];
        srel[t*3+1] = pqb[Nc + nq]   - psb[Mc + iv];
        srel[t*3+2] = pqb[2*Nc + nq] - psb[2*Mc + iv];
    }
    __syncthreads();
    int d = t & 63, slot = t >> 6;
    float w0 = Wp1[d*3], w1 = Wp1[d*3+1], w2 = Wp1[d*3+2], bb = bp1[d];
    float s = 0.f, s2 = 0.f;
    int i0 = slot*64;
    for (int i = i0; i < i0+64; i++) {
        float x = fmaf(w0, srel[i*3], fmaf(w1, srel[i*3+1], fmaf(w2, srel[i*3+2], bb)));
        g_pe[(size_t)(p0 + i)*Dc + d] = x;
        s += x; s2 += x*x;
    }
    ssum[slot*64 + d] = s;
    ssq[slot*64 + d] = s2;
    __syncthreads();
    if (t < 64) {
        float ts = ssum[t] + ssum[64+t] + ssum[128+t] + ssum[192+t];
        float tq = ssq[t]  + ssq[64+t]  + ssq[128+t]  + ssq[192+t];
        atomicAdd(&g_sum1[t], (double)ts);
        atomicAdd(&g_sq1[t],  (double)tq);
    }
}

// ---------------- pe = Wp2 @ relu(BN1(pe1)) + bp2 ; a1 = Wa1 @ (q-k+pe) + ba1
__global__ __launch_bounds__(512, 2)
void pe2_a1_kernel(const float* __restrict__ Wp2, const float* __restrict__ bp2,
                   const float* __restrict__ gp,  const float* __restrict__ btp,
                   const float* __restrict__ Wa1, const float* __restrict__ ba1) {
    extern __shared__ float sm6[];
    float* sWp2  = sm6;                 // [64 d][64 e]
    float* sWa1h = sWp2 + Dc*Dc;        // [128 h][64 e] (one half)
    float* sX    = sWa1h + 128*Dc;      // [64 e][128 pt]
    float* sbn   = sX + Dc*128;         // 64
    float* ssh   = sbn + Dc;            // 64
    float* sbp2  = ssh + Dc;            // 64
    float* sba1  = sbp2 + Dc;           // 256
    int t = threadIdx.x;
    for (int i = t; i < Dc*Dc/4; i += 512) ((float4*)sWp2)[i] = ((const float4*)Wp2)[i];
    if (t < Dc) {
        const double inv = 1.0 / (double)NPTS;
        double m = g_sum1[t]*inv;
        double v = g_sq1[t]*inv - m*m;
        float rs = rsqrtf((float)v + EPSf);
        float sc = gp[t] * rs;
        sbn[t] = sc;
        ssh[t] = btp[t] - (float)m*sc;
        sbp2[t] = bp2[t];
    }
    if (t < Hc) sba1[t] = ba1[t];
    int p0 = blockIdx.x * 128;
    __syncthreads();
    // load pe1 tile transposed, apply BN1+relu
    for (int f = t; f < 2048; f += 512) {
        int d4 = f >> 7, ptl = f & 127;
        float4 v = *(const float4*)&g_pe[(size_t)(p0 + ptl)*Dc + d4*4];
        int d = d4*4;
        sX[(d+0)*128 + ptl] = fmaxf(fmaf(v.x, sbn[d+0], ssh[d+0]), 0.f);
        sX[(d+1)*128 + ptl] = fmaxf(fmaf(v.y, sbn[d+1], ssh[d+1]), 0.f);
        sX[(d+2)*128 + ptl] = fmaxf(fmaf(v.z, sbn[d+2], ssh[d+2]), 0.f);
        sX[(d+3)*128 + ptl] = fmaxf(fmaf(v.w, sbn[d+3], ssh[d+3]), 0.f);
    }
    __syncthreads();
    // -------- Stage 1 GEMM: pe = Wp2 @ Xr (4d x 4pt) --------
    int og2 = t >> 5, pg2 = t & 31;
    int d0 = og2*4, pt0s = pg2*4;
    u64 acc1[4][2];
    #pragma unroll
    for (int q = 0; q < 4; q++) { acc1[q][0] = 0ull; acc1[q][1] = 0ull; }
    #pragma unroll 4
    for (int e = 0; e < Dc; e++) {
        ulonglong2 x2 = *(const ulonglong2*)&sX[e*128 + pt0s];
        #pragma unroll
        for (int q = 0; q < 4; q++) {
            float w = sWp2[(d0+q)*Dc + e];
            u64 wp = pack2(w, w);
            acc1[q][0] = fma2(wp, x2.x, acc1[q][0]);
            acc1[q][1] = fma2(wp, x2.y, acc1[q][1]);
        }
    }
    __syncthreads();
    // epilogue 1: write pe; S = pe + q - k into sX
    {
        float vx[4][4];
        #pragma unroll
        for (int q = 0; q < 4; q++) {
            float2 lo = unpack2(acc1[q][0]), hi = unpack2(acc1[q][1]);
            float bb = sbp2[d0+q];
            vx[q][0] = lo.x + bb; vx[q][1] = lo.y + bb;
            vx[q][2] = hi.x + bb; vx[q][3] = hi.y + bb;
        }
        #pragma unroll
        for (int j = 0; j < 4; j++) {
            int pt = p0 + pt0s + j;
            int b  = pt >> 15;
            int nq = (pt & 32767) >> 4;
            int iv = g_idx[pt];
            float4 q4 = *(const float4*)&g_q[((size_t)b*Nc + nq)*Dc + d0];
            float4 k4 = *(const float4*)&g_k[((size_t)b*Mc + iv)*Dc + d0];
            float4 pe4 = make_float4(vx[0][j], vx[1][j], vx[2][j], vx[3][j]);
            *(float4*)&g_pe[(size_t)pt*Dc + d0] = pe4;
            sX[(d0+0)*128 + pt0s + j] = pe4.x + q4.x - k4.x;
            sX[(d0+1)*128 + pt0s + j] = pe4.y + q4.y - k4.y;
            sX[(d0+2)*128 + pt0s + j] = pe4.z + q4.z - k4.z;
            sX[(d0+3)*128 + pt0s + j] = pe4.w + q4.w - k4.w;
        }
    }
    // -------- Stage 2 GEMM: a1 = Wa1 @ S, two 128-h halves, 4h x 8pt tiles --
    int og = t >> 4, pg = t & 15;      // og 0..31, pg 0..15
    int pt0 = pg*8;
    for (int half = 0; half < 2; half++) {
        __syncthreads();   // S complete (half 0) / previous half reads done
        const float4* Wsrc = (const float4*)(Wa1 + (size_t)half*128*Dc);
        for (int i = t; i < 2048; i += 512) ((float4*)sWa1h)[i] = Wsrc[i];
        __syncthreads();
        u64 a[4][4];
        #pragma unroll
        for (int q = 0; q < 4; q++)
            #pragma unroll
            for (int j = 0; j < 4; j++) a[q][j] = 0ull;
        #pragma unroll 2
        for (int e = 0; e < Dc; e++) {
            ulonglong2 xa = *(const ulonglong2*)&sX[e*128 + pt0];
            ulonglong2 xb = *(const ulonglong2*)&sX[e*128 + pt0 + 4];
            #pragma unroll
            for (int q = 0; q < 4; q++) {
                float w = sWa1h[(og*4+q)*Dc + e];
                u64 wp = pack2(w, w);
                a[q][0] = fma2(wp, xa.x, a[q][0]);
                a[q][1] = fma2(wp, xa.y, a[q][1]);
                a[q][2] = fma2(wp, xb.x, a[q][2]);
                a[q][3] = fma2(wp, xb.y, a[q][3]);
            }
        }
        #pragma unroll
        for (int q = 0; q < 4; q++) {
            int h = half*128 + og*4 + q;
            float bias = sba1[h];
            float vv[8];
            #pragma unroll
            for (int j = 0; j < 4; j++) {
                float2 u = unpack2(a[q][j]);
                vv[j*2+0] = u.x + bias;
                vv[j*2+1] = u.y + bias;
            }
            float s = 0.f, s2 = 0.f;
            #pragma unroll
            for (int j = 0; j < 8; j++) { s += vv[j]; s2 += vv[j]*vv[j]; }
            float* op = &g_a1[(size_t)h*NPTS + p0 + pt0];
            *(float4*)op       = make_float4(vv[0], vv[1], vv[2], vv[3]);
            *(float4*)(op + 4) = make_float4(vv[4], vv[5], vv[6], vv[7]);
            #pragma unroll
            for (int off = 8; off > 0; off >>= 1) {
                s  += __shfl_xor_sync(0xffffffffu, s, off);
                s2 += __shfl_xor_sync(0xffffffffu, s2, off);
            }
            if (pg == 0) {
                atomicAdd(&g_sum2[h], (double)s);
                atomicAdd(&g_sq2[h],  (double)s2);
            }
        }
    }
}

// ---------------- a2 = Wa2 @ relu(BN2(a1)) + ba2 ; softmax; aggregate ------
__global__ __launch_bounds__(512, 2)
void a2_softagg_kernel(const float* __restrict__ Wa2, const float* __restrict__ ba2,
                       const float* __restrict__ ga,  const float* __restrict__ bta) {
    extern __shared__ float sm7[];
    float* sW   = sm7;             // [64 d][64 hl]
    float* sA   = sW + Dc*64;      // [64 hl][128 pt]; later sOut [128 pt][65]
    float* ssc  = sA + 8320;       // 256
    float* ssh2 = ssc + Hc;        // 256
    float* sba2 = ssh2 + Hc;       // 64
    int t = threadIdx.x;
    int p0 = blockIdx.x * 128;
    int b  = p0 >> 15;
    if (t < Hc) {
        const double inv = 1.0 / (double)NPTS;
        double m = g_sum2[t]*inv;
        double v = g_sq2[t]*inv - m*m;
        float rs = rsqrtf((float)v + EPSf);
        float sc = ga[t] * rs;
        ssc[t] = sc;
        ssh2[t] = bta[t] - (float)m*sc;
    }
    if (t < Dc) sba2[t] = ba2[t];
    int og3 = t >> 5, pg3 = t & 31;
    int d0 = og3*4, pt0 = pg3*4;
    u64 acc[4][2];
    #pragma unroll
    for (int q = 0; q < 4; q++) { acc[q][0] = 0ull; acc[q][1] = 0ull; }
    for (int ks = 0; ks < 4; ks++) {
        int h0k = ks*64;
        __syncthreads();
        for (int i = t; i < 1024; i += 512) {
            int d = i >> 4, hl4 = i & 15;
            ((float4*)&sW[d*64])[hl4] = *(const float4*)&Wa2[(size_t)d*Hc + h0k + hl4*4];
        }
        for (int f = t; f < 2048; f += 512) {
            int hl = f >> 5, pt4 = f & 31;
            int h = h0k + hl;
            float4 v = *(const float4*)&g_a1[(size_t)h*NPTS + p0 + pt4*4];
            float sc = ssc[h], sh = ssh2[h];
            float4 o = make_float4(fmaxf(fmaf(v.x, sc, sh), 0.f),
                                   fmaxf(fmaf(v.y, sc, sh), 0.f),
                                   fmaxf(fmaf(v.z, sc, sh), 0.f),
                                   fmaxf(fmaf(v.w, sc, sh), 0.f));
            *(float4*)&sA[hl*128 + pt4*4] = o;
        }
        __syncthreads();
        #pragma unroll 4
        for (int hl = 0; hl < 64; hl++) {
            ulonglong2 x2 = *(const ulonglong2*)&sA[hl*128 + pt0];
            #pragma unroll
            for (int q = 0; q < 4; q++) {
                float w = sW[(d0+q)*64 + hl];
                u64 wp = pack2(w, w);
                acc[q][0] = fma2(wp, x2.x, acc[q][0]);
                acc[q][1] = fma2(wp, x2.y, acc[q][1]);
            }
        }
    }
    __syncthreads();
    float* sOut = sA;
    {
        float vx[4][4];
        #pragma unroll
        for (int q = 0; q < 4; q++) {
            float2 lo = unpack2(acc[q][0]), hi = unpack2(acc[q][1]);
            float bb = sba2[d0+q];
            vx[q][0] = lo.x + bb; vx[q][1] = lo.y + bb;
            vx[q][2] = hi.x + bb; vx[q][3] = hi.y + bb;
        }
        #pragma unroll
        for (int j = 0; j < 4; j++) {
            int pt = pt0 + j;
            sOut[pt*65 + d0+0] = vx[0][j];
            sOut[pt*65 + d0+1] = vx[1][j];
            sOut[pt*65 + d0+2] = vx[2][j];
            sOut[pt*65 + d0+3] = vx[3][j];
        }
    }
    __syncthreads();
    int d  = t & 63;
    int nl = t >> 6;
    int base = nl*16;
    float av[Kc];
    float mx = -3.4e38f;
    #pragma unroll
    for (int k = 0; k < Kc; k++) {
        av[k] = sOut[(base + k)*65 + d];
        mx = fmaxf(mx, av[k]);
    }
    float sum = 0.f;
    #pragma unroll
    for (int k = 0; k < Kc; k++) { av[k] = __expf(av[k] - mx); sum += av[k]; }
    float inv = 1.f / sum;
    const int* ip = g_idx + p0 + base;
    float agg = 0.f;
    #pragma unroll
    for (int k = 0; k < Kc; k++) {
        int iv = ip[k];
        float vg = g_v[((size_t)b*Mc + iv)*Dc + d];
        float pe = g_pe[(size_t)(p0 + base + k)*Dc + d];
        agg = fmaf(av[k]*inv, vg + pe, agg);
    }
    int bn = (p0 >> 4) + nl;
    g_agg[(size_t)bn*Dc + d] = agg;
}

// ---------------- out = We @ agg + be + fq ---------------------------------
__global__ __launch_bounds__(512, 2)
void final_kernel(const float* __restrict__ We, const float* __restrict__ be,
                  const float* __restrict__ fq, float* __restrict__ out) {
    extern __shared__ float sm8[];
    float* sWe = sm8;              // [128 c][64 d]
    float* sG  = sWe + Cc*Dc;      // [64 d][128 n]
    float* sbe = sG + Dc*128;      // 128
    int t = threadIdx.x;
    int b = blockIdx.y;
    int nblk = blockIdx.x * 128;
    for (int i = t; i < Cc*Dc/4; i += 512) ((float4*)sWe)[i] = ((const float4*)We)[i];
    if (t < Cc) sbe[t] = be[t];
    for (int f = t; f < 2048; f += 512) {
        int d4 = f >> 7, nl = f & 127;
        float4 v = *(const float4*)&g_agg[((size_t)b*Nc + nblk + nl)*Dc + d4*4];
        int d = d4*4;
        sG[(d+0)*128 + nl] = v.x;
        sG[(d+1)*128 + nl] = v.y;
        sG[(d+2)*128 + nl] = v.z;
        sG[(d+3)*128 + nl] = v.w;
    }
    __syncthreads();
    int og = t >> 4, pg = t & 15;
    int c0 = og*4, n0 = pg*8;
    u64 acc[4][4];
    #pragma unroll
    for (int q = 0; q < 4; q++)
        #pragma unroll
        for (int j = 0; j < 4; j++) acc[q][j] = 0ull;
    #pragma unroll 2
    for (int e = 0; e < Dc; e++) {
        ulonglong2 xa = *(const ulonglong2*)&sG[e*128 + n0];
        ulonglong2 xb = *(const ulonglong2*)&sG[e*128 + n0 + 4];
        #pragma unroll
        for (int q = 0; q < 4; q++) {
            float w = sWe[(c0+q)*Dc + e];
            u64 wp = pack2(w, w);
            acc[q][0] = fma2(wp, xa.x, acc[q][0]);
            acc[q][1] = fma2(wp, xa.y, acc[q][1]);
            acc[q][2] = fma2(wp, xb.x, acc[q][2]);
            acc[q][3] = fma2(wp, xb.y, acc[q][3]);
        }
    }
    #pragma unroll
    for (int q = 0; q < 4; q++) {
        int c = c0 + q;
        float bc = sbe[c];
        float vv[8];
        #pragma unroll
        for (int j = 0; j < 4; j++) {
            float2 u = unpack2(acc[q][j]);
            vv[j*2+0] = u.x; vv[j*2+1] = u.y;
        }
        size_t o = (size_t)b*Cc*Nc + (size_t)c*Nc + nblk + n0;
        float4 f0 = *(const float4*)&fq[o];
        float4 f1 = *(const float4*)&fq[o + 4];
        *(float4*)&out[o]     = make_float4(vv[0]+bc+f0.x, vv[1]+bc+f0.y,
                                            vv[2]+bc+f0.z, vv[3]+bc+f0.w);
        *(float4*)&out[o + 4] = make_float4(vv[4]+bc+f1.x, vv[5]+bc+f1.y,
                                            vv[6]+bc+f1.z, vv[7]+bc+f1.w);
    }
}

// ---------------- launch -----------------------------------------------------
extern "C" void kernel_launch(void* const* d_in, const int* in_sizes, int n_in,
                              void* d_out, int out_size) {
    const float* pq  = (const float*)d_in[0];
    const float* fq  = (const float*)d_in[1];
    const float* ps  = (const float*)d_in[2];
    const float* fs  = (const float*)d_in[3];
    const float* Wq  = (const float*)d_in[4];  const float* bq  = (const float*)d_in[5];
    const float* Wk  = (const float*)d_in[6];  const float* bk  = (const float*)d_in[7];
    const float* Wv  = (const float*)d_in[8];  const float* bv  = (const float*)d_in[9];
    const float* Wp1 = (const float*)d_in[10]; const float* bp1 = (const float*)d_in[11];
    const float* gp  = (const float*)d_in[12]; const float* btp = (const float*)d_in[13];
    const float* Wp2 = (const float*)d_in[14]; const float* bp2 = (const float*)d_in[15];
    const float* Wa1 = (const float*)d_in[16]; const float* ba1 = (const float*)d_in[17];
    const float* ga  = (const float*)d_in[18]; const float* bta = (const float*)d_in[19];
    const float* Wa2 = (const float*)d_in[20]; const float* ba2 = (const float*)d_in[21];
    const float* We  = (const float*)d_in[22]; const float* be  = (const float*)d_in[23];
    float* out = (float*)d_out;

    const int SMEM_QKV = (Dc*Cc + 32*128 + Dc) * (int)sizeof(float);
    const int SMEM_KNN = 2048*16 + 64*65*4*2;
    const int SMEM_PA  = (Dc*Dc + 128*Dc + Dc*128 + 3*Dc + Hc) * (int)sizeof(float);
    const int SMEM_A2  = (Dc*64 + 8320 + 2*Hc + Dc) * (int)sizeof(float);
    const int SMEM_FIN = (Cc*Dc + Dc*128 + Cc) * (int)sizeof(float);
    cudaFuncSetAttribute(qkv_kernel,        cudaFuncAttributeMaxDynamicSharedMemorySize, SMEM_QKV);
    cudaFuncSetAttribute(knn_kernel,        cudaFuncAttributeMaxDynamicSharedMemorySize, SMEM_KNN);
    cudaFuncSetAttribute(pe2_a1_kernel,     cudaFuncAttributeMaxDynamicSharedMemorySize, SMEM_PA);
    cudaFuncSetAttribute(a2_softagg_kernel, cudaFuncAttributeMaxDynamicSharedMemorySize, SMEM_A2);
    cudaFuncSetAttribute(final_kernel,      cudaFuncAttributeMaxDynamicSharedMemorySize, SMEM_FIN);

    qkv_kernel<<<dim3(Nc/128, 12), 512, SMEM_QKV>>>(fq, fs, Wq, bq, Wk, bk, Wv, bv);
    knn_kernel<<<dim3(Nc/64, Bc), 256, SMEM_KNN>>>(pq, ps);
    pe1_stats_kernel<<<NPTS/256, 256>>>(pq, ps, Wp1, bp1);
    pe2_a1_kernel<<<NPTS/128, 512, SMEM_PA>>>(Wp2, bp2, gp, btp, Wa1, ba1);
    a2_softagg_kernel<<<NPTS/128, 512, SMEM_A2>>>(Wa2, ba2, ga, bta);
    final_kernel<<<dim3(Nc/128, Bc), 512, SMEM_FIN>>>(We, be, fq, out);
}

// round 6
// speedup vs baseline: 2.3760x; 1.1225x over previous
#include <cuda_runtime.h>
#include <math.h>

#define Bc 4
#define Cc 128
#define Dc 64
#define Nc 2048
#define Mc 2048
#define Hc 256
#define Kc 16
#define NPTS (Bc*Nc*Kc)   // 131072
#define EPSf 1e-5f

typedef unsigned long long u64;

__device__ __forceinline__ u64 pack2(float lo, float hi) {
    u64 r; asm("mov.b64 %0, {%1,%2};" : "=l"(r) : "f"(lo), "f"(hi)); return r;
}
__device__ __forceinline__ float2 unpack2(u64 v) {
    float2 r; asm("mov.b64 {%0,%1}, %2;" : "=f"(r.x), "=f"(r.y) : "l"(v)); return r;
}
__device__ __forceinline__ u64 fma2(u64 a, u64 b, u64 c) {
    u64 d; asm("fma.rn.f32x2 %0, %1, %2, %3;" : "=l"(d) : "l"(a), "l"(b), "l"(c)); return d;
}

// ---------------- scratch -----------------------------------------------
__device__ __align__(256) float g_q[Bc*Nc*Dc];
__device__ __align__(256) float g_k[Bc*Mc*Dc];
__device__ __align__(256) float g_v[Bc*Mc*Dc];
__device__ __align__(256) int   g_idx[NPTS];
__device__ __align__(256) float g_pe[NPTS*Dc];
__device__ __align__(256) float g_a1[(size_t)NPTS*Hc];    // [h][pt]
__device__ __align__(256) float g_agg[Bc*Nc*Dc];
__device__ double g_sum1[Dc], g_sq1[Dc];
__device__ double g_sum2[Hc], g_sq2[Hc];
// transposed weights
__device__ __align__(256) float g_Wqt[Cc*Dc];   // [c][d]
__device__ __align__(256) float g_Wkt[Cc*Dc];
__device__ __align__(256) float g_Wvt[Cc*Dc];
__device__ __align__(256) float g_Wp2t[Dc*Dc];  // [e][d]
__device__ __align__(256) float g_Wa1t[Dc*Hc];  // [e][h]
__device__ __align__(256) float g_Wa2t[Hc*Dc];  // [h][d]
__device__ __align__(256) float g_Wet[Dc*Cc];   // [d][c]

// ---------------- prep: transpose weights ----------------------------------
__global__ void prep_kernel(const float* __restrict__ Wq, const float* __restrict__ Wk,
                            const float* __restrict__ Wv, const float* __restrict__ Wp2,
                            const float* __restrict__ Wa1, const float* __restrict__ Wa2,
                            const float* __restrict__ We) {
    int job = blockIdx.y;
    int i0 = blockIdx.x * 256 + threadIdx.x;
    int stride = gridDim.x * 256;
    if (job == 0) { for (int i = i0; i < Cc*Dc; i += stride) { int c = i/Dc, d = i%Dc; g_Wqt[i]  = Wq[d*Cc + c]; } }
    else if (job == 1) { for (int i = i0; i < Cc*Dc; i += stride) { int c = i/Dc, d = i%Dc; g_Wkt[i]  = Wk[d*Cc + c]; } }
    else if (job == 2) { for (int i = i0; i < Cc*Dc; i += stride) { int c = i/Dc, d = i%Dc; g_Wvt[i]  = Wv[d*Cc + c]; } }
    else if (job == 3) { for (int i = i0; i < Dc*Dc; i += stride) { int e = i/Dc, d = i%Dc; g_Wp2t[i] = Wp2[d*Dc + e]; } }
    else if (job == 4) { for (int i = i0; i < Dc*Hc; i += stride) { int e = i/Hc, h = i%Hc; g_Wa1t[i] = Wa1[h*Dc + e]; } }
    else if (job == 5) { for (int i = i0; i < Hc*Dc; i += stride) { int h = i/Dc, d = i%Dc; g_Wa2t[i] = Wa2[d*Hc + h]; } }
    else               { for (int i = i0; i < Dc*Cc; i += stride) { int d = i/Cc, c = i%Cc; g_Wet[i]  = We[c*Dc + d]; } }
}

// ---------------- q/k/v 1x1 convs as tiled GEMM ----------------------------
__global__ __launch_bounds__(512, 2)
void qkv_kernel(const float* __restrict__ fq, const float* __restrict__ fs,
                const float* __restrict__ bq, const float* __restrict__ bk,
                const float* __restrict__ bv) {
    extern __shared__ float sm0[];
    float* sWt = sm0;           // [128 c][64 d] transposed
    float* sF = sWt + Cc*Dc;    // [32 c][128 n]
    float* sb = sF + 32*128;    // 64
    int zw = blockIdx.y;
    int which = zw >> 2, b = zw & 3;
    const float* f    = (which == 0) ? fq : fs;
    const float* Wt   = (which == 0) ? g_Wqt : (which == 1 ? g_Wkt : g_Wvt);
    const float* bias = (which == 0) ? bq : (which == 1 ? bk : bv);
    float* out        = (which == 0) ? g_q : (which == 1 ? g_k : g_v);
    int t = threadIdx.x;
    for (int i = t; i < Cc*Dc/4; i += 512) ((float4*)sWt)[i] = ((const float4*)Wt)[i];
    if (t < Dc) sb[t] = bias[t];
    int nblk = blockIdx.x * 128;
    const float* fb = f + (size_t)b*Cc*Nc + nblk;
    int og = t >> 5, pg = t & 31;
    int d0 = og*4, n0 = pg*4;
    u64 acc[4][2];
    #pragma unroll
    for (int q = 0; q < 4; q++) { acc[q][0] = 0ull; acc[q][1] = 0ull; }
    for (int ks = 0; ks < 4; ks++) {
        int c0 = ks*32;
        __syncthreads();
        for (int i = t; i < 1024; i += 512) {
            int cl = i >> 5, nl4 = (i & 31);
            ((float4*)sF)[cl*32 + nl4] = *(const float4*)&fb[(size_t)(c0 + cl)*Nc + nl4*4];
        }
        __syncthreads();
        #pragma unroll 4
        for (int cl = 0; cl < 32; cl++) {
            ulonglong2 x2 = *(const ulonglong2*)&sF[cl*128 + n0];
            float4 w4 = *(const float4*)&sWt[(c0+cl)*Dc + d0];
            u64 w0 = pack2(w4.x, w4.x), w1 = pack2(w4.y, w4.y);
            u64 w2 = pack2(w4.z, w4.z), w3 = pack2(w4.w, w4.w);
            acc[0][0] = fma2(w0, x2.x, acc[0][0]); acc[0][1] = fma2(w0, x2.y, acc[0][1]);
            acc[1][0] = fma2(w1, x2.x, acc[1][0]); acc[1][1] = fma2(w1, x2.y, acc[1][1]);
            acc[2][0] = fma2(w2, x2.x, acc[2][0]); acc[2][1] = fma2(w2, x2.y, acc[2][1]);
            acc[3][0] = fma2(w3, x2.x, acc[3][0]); acc[3][1] = fma2(w3, x2.y, acc[3][1]);
        }
    }
    float b0 = sb[d0], b1 = sb[d0+1], b2 = sb[d0+2], b3 = sb[d0+3];
    float vx[4][4];
    #pragma unroll
    for (int q = 0; q < 4; q++) {
        float2 lo = unpack2(acc[q][0]), hi = unpack2(acc[q][1]);
        vx[q][0]=lo.x; vx[q][1]=lo.y; vx[q][2]=hi.x; vx[q][3]=hi.y;
    }
    #pragma unroll
    for (int j = 0; j < 4; j++) {
        int n = nblk + n0 + j;
        float4 o = make_float4(vx[0][j]+b0, vx[1][j]+b1, vx[2][j]+b2, vx[3][j]+b3);
        *(float4*)&out[((size_t)b*Nc + n)*Dc + d0] = o;
    }
}

// ---------------- KNN: 4 threads/query, chunked scan + merge ---------------
__global__ __launch_bounds__(256, 2)
void knn_kernel(const float* __restrict__ pq, const float* __restrict__ ps) {
    extern __shared__ float smk[];
    float4* sp = (float4*)smk;          // 2048 float4 = 32 KB
    float*  cd = smk + 2048*4;
    int*    ci = (int*)(cd + 64*65);
    int t = threadIdx.x;
    int b = blockIdx.y;
    if (blockIdx.x == 0 && blockIdx.y == 0) {
        if (t < Dc) { g_sum1[t] = 0.0; g_sq1[t] = 0.0; }
        g_sum2[t] = 0.0; g_sq2[t] = 0.0;
    }
    const float* p = ps + (size_t)b*3*Mc;
    for (int i = t; i < Mc; i += 256) {
        float x = p[i], y = p[Mc + i], z = p[2*Mc + i];
        sp[i] = make_float4(x, y, z, x*x + y*y + z*z);
    }
    __syncthreads();
    int qi = t & 63, chunk = t >> 6;
    int n = blockIdx.x * 64 + qi;
    const float* pqb = pq + (size_t)b*3*Nc;
    float qx = pqb[n], qy = pqb[Nc + n], qz = pqb[2*Nc + n];
    float qq = qx*qx + qy*qy + qz*qz;
    float bd[Kc]; int bi[Kc];
    #pragma unroll
    for (int j = 0; j < Kc; j++) { bd[j] = 3.4e38f; bi[j] = 0; }
    float worst = 3.4e38f; int wpos = 0;
    int m0 = chunk*512;
    #pragma unroll 2
    for (int mm = 0; mm < 512; mm++) {
        int m = m0 + mm;
        float4 c = sp[m];
        float dot = qx*c.x + qy*c.y + qz*c.z;
        float d2 = qq + c.w - 2.0f*dot;
        if (d2 < worst) {
            #pragma unroll
            for (int j = 0; j < Kc; j++) if (j == wpos) { bd[j] = d2; bi[j] = m; }
            worst = -3.4e38f;
            #pragma unroll
            for (int j = 0; j < Kc; j++) if (bd[j] > worst) { worst = bd[j]; wpos = j; }
        }
    }
    #pragma unroll
    for (int j = 0; j < Kc; j++) {
        cd[qi*65 + chunk*16 + j] = bd[j];
        ci[qi*65 + chunk*16 + j] = bi[j];
    }
    __syncthreads();
    if (t < 64) {
        float fd[Kc]; int fi[Kc];
        #pragma unroll
        for (int j = 0; j < Kc; j++) { fd[j] = 3.4e38f; fi[j] = 0; }
        float w2 = 3.4e38f; int wp2 = 0;
        for (int c = 0; c < 64; c++) {
            float d2 = cd[t*65 + c];
            int   iv = ci[t*65 + c];
            if (d2 < w2) {
                #pragma unroll
                for (int j = 0; j < Kc; j++) if (j == wp2) { fd[j] = d2; fi[j] = iv; }
                w2 = -3.4e38f;
                #pragma unroll
                for (int j = 0; j < Kc; j++) if (fd[j] > w2) { w2 = fd[j]; wp2 = j; }
            }
        }
        int nn = blockIdx.x * 64 + t;
        int* o = g_idx + ((size_t)b*Nc + nn)*Kc;
        #pragma unroll
        for (int j = 0; j < Kc; j++) o[j] = fi[j];
    }
}

// ---------------- pe1 = Wp1 @ pos_rel + bp1, fused BN1 stats ---------------
__global__ __launch_bounds__(256, 4)
void pe1_stats_kernel(const float* __restrict__ pq, const float* __restrict__ ps,
                      const float* __restrict__ Wp1, const float* __restrict__ bp1) {
    __shared__ float srel[256*3];
    __shared__ float ssum[4*64], ssq[4*64];
    int p0 = blockIdx.x * 256;
    int t = threadIdx.x;
    {
        int p = p0 + t;
        int b = p >> 15;
        int nq = (p & 32767) >> 4;
        int iv = g_idx[p];
        const float* pqb = pq + (size_t)b*3*Nc;
        const float* psb = ps + (size_t)b*3*Mc;
        srel[t*3+0] = pqb[nq]        - psb[iv];
        srel[t*3+1] = pqb[Nc + nq]   - psb[Mc + iv];
        srel[t*3+2] = pqb[2*Nc + nq] - psb[2*Mc + iv];
    }
    __syncthreads();
    int d = t & 63, slot = t >> 6;
    float w0 = Wp1[d*3], w1 = Wp1[d*3+1], w2 = Wp1[d*3+2], bb = bp1[d];
    float s = 0.f, s2 = 0.f;
    int i0 = slot*64;
    for (int i = i0; i < i0+64; i++) {
        float x = fmaf(w0, srel[i*3], fmaf(w1, srel[i*3+1], fmaf(w2, srel[i*3+2], bb)));
        g_pe[(size_t)(p0 + i)*Dc + d] = x;
        s += x; s2 += x*x;
    }
    ssum[slot*64 + d] = s;
    ssq[slot*64 + d] = s2;
    __syncthreads();
    if (t < 64) {
        float ts = ssum[t] + ssum[64+t] + ssum[128+t] + ssum[192+t];
        float tq = ssq[t]  + ssq[64+t]  + ssq[128+t]  + ssq[192+t];
        atomicAdd(&g_sum1[t], (double)ts);
        atomicAdd(&g_sq1[t],  (double)tq);
    }
}

// ---------------- pe = Wp2 @ relu(BN1(pe1)) + bp2 ; a1 = Wa1 @ (q-k+pe) + ba1
// Stage1: 4d x 4pt. Stage2: single pass 8h x 8pt with Wa1t [e][h] in smem.
__global__ __launch_bounds__(512, 1)
void pe2_a1_kernel(const float* __restrict__ bp2,
                   const float* __restrict__ gp,  const float* __restrict__ btp,
                   const float* __restrict__ ba1) {
    extern __shared__ float sm6[];
    float* sW   = sm6;                 // 16384 floats: first Wp2t [e][d], then Wa1t [e][h]
    float* sX   = sW + 16384;          // [64 e][128 pt]
    float* sbn  = sX + Dc*128;         // 64
    float* ssh  = sbn + Dc;            // 64
    float* sbp2 = ssh + Dc;            // 64
    float* sba1 = sbp2 + Dc;           // 256
    int t = threadIdx.x;
    for (int i = t; i < Dc*Dc/4; i += 512) ((float4*)sW)[i] = ((const float4*)g_Wp2t)[i];
    if (t < Dc) {
        const double inv = 1.0 / (double)NPTS;
        double m = g_sum1[t]*inv;
        double v = g_sq1[t]*inv - m*m;
        float rs = rsqrtf((float)v + EPSf);
        float sc = gp[t] * rs;
        sbn[t] = sc;
        ssh[t] = btp[t] - (float)m*sc;
        sbp2[t] = bp2[t];
    }
    if (t < Hc) sba1[t] = ba1[t];
    int p0 = blockIdx.x * 128;
    __syncthreads();
    // load pe1 tile transposed, apply BN1+relu
    for (int f = t; f < 2048; f += 512) {
        int d4 = f >> 7, ptl = f & 127;
        float4 v = *(const float4*)&g_pe[(size_t)(p0 + ptl)*Dc + d4*4];
        int d = d4*4;
        sX[(d+0)*128 + ptl] = fmaxf(fmaf(v.x, sbn[d+0], ssh[d+0]), 0.f);
        sX[(d+1)*128 + ptl] = fmaxf(fmaf(v.y, sbn[d+1], ssh[d+1]), 0.f);
        sX[(d+2)*128 + ptl] = fmaxf(fmaf(v.z, sbn[d+2], ssh[d+2]), 0.f);
        sX[(d+3)*128 + ptl] = fmaxf(fmaf(v.w, sbn[d+3], ssh[d+3]), 0.f);
    }
    __syncthreads();
    // -------- Stage 1 GEMM: pe = Wp2 @ Xr (4d x 4pt) --------
    int og2 = t >> 5, pg2 = t & 31;
    int d0 = og2*4, pt0s = pg2*4;
    u64 acc1[4][2];
    #pragma unroll
    for (int q = 0; q < 4; q++) { acc1[q][0] = 0ull; acc1[q][1] = 0ull; }
    #pragma unroll 4
    for (int e = 0; e < Dc; e++) {
        ulonglong2 x2 = *(const ulonglong2*)&sX[e*128 + pt0s];
        float4 w4 = *(const float4*)&sW[e*Dc + d0];
        u64 w0 = pack2(w4.x, w4.x), w1 = pack2(w4.y, w4.y);
        u64 w2 = pack2(w4.z, w4.z), w3 = pack2(w4.w, w4.w);
        acc1[0][0] = fma2(w0, x2.x, acc1[0][0]); acc1[0][1] = fma2(w0, x2.y, acc1[0][1]);
        acc1[1][0] = fma2(w1, x2.x, acc1[1][0]); acc1[1][1] = fma2(w1, x2.y, acc1[1][1]);
        acc1[2][0] = fma2(w2, x2.x, acc1[2][0]); acc1[2][1] = fma2(w2, x2.y, acc1[2][1]);
        acc1[3][0] = fma2(w3, x2.x, acc1[3][0]); acc1[3][1] = fma2(w3, x2.y, acc1[3][1]);
    }
    __syncthreads();   // stage1 reads of sW + sX done
    // epilogue 1: write pe; S = pe + q - k into sX; also stage Wa1t into sW
    {
        float vx[4][4];
        #pragma unroll
        for (int q = 0; q < 4; q++) {
            float2 lo = unpack2(acc1[q][0]), hi = unpack2(acc1[q][1]);
            float bb = sbp2[d0+q];
            vx[q][0] = lo.x + bb; vx[q][1] = lo.y + bb;
            vx[q][2] = hi.x + bb; vx[q][3] = hi.y + bb;
        }
        #pragma unroll
        for (int j = 0; j < 4; j++) {
            int pt = p0 + pt0s + j;
            int b  = pt >> 15;
            int nq = (pt & 32767) >> 4;
            int iv = g_idx[pt];
            float4 q4 = *(const float4*)&g_q[((size_t)b*Nc + nq)*Dc + d0];
            float4 k4 = *(const float4*)&g_k[((size_t)b*Mc + iv)*Dc + d0];
            float4 pe4 = make_float4(vx[0][j], vx[1][j], vx[2][j], vx[3][j]);
            *(float4*)&g_pe[(size_t)pt*Dc + d0] = pe4;
            sX[(d0+0)*128 + pt0s + j] = pe4.x + q4.x - k4.x;
            sX[(d0+1)*128 + pt0s + j] = pe4.y + q4.y - k4.y;
            sX[(d0+2)*128 + pt0s + j] = pe4.z + q4.z - k4.z;
            sX[(d0+3)*128 + pt0s + j] = pe4.w + q4.w - k4.w;
        }
    }
    for (int i = t; i < 4096; i += 512) ((float4*)sW)[i] = ((const float4*)g_Wa1t)[i];
    __syncthreads();
    // -------- Stage 2 GEMM: a1 = Wa1 @ S, 8h x 8pt, single pass ------------
    int og = t >> 4, pg = t & 15;
    int h0 = og*8, pt0 = pg*8;
    u64 a[8][4];
    #pragma unroll
    for (int hh = 0; hh < 8; hh++)
        #pragma unroll
        for (int j = 0; j < 4; j++) a[hh][j] = 0ull;
    for (int e = 0; e < Dc; e++) {
        ulonglong2 xa = *(const ulonglong2*)&sX[e*128 + pt0];
        ulonglong2 xb = *(const ulonglong2*)&sX[e*128 + pt0 + 4];
        float4 wa = *(const float4*)&sW[e*Hc + h0];
        float4 wb = *(const float4*)&sW[e*Hc + h0 + 4];
        float wf[8] = {wa.x, wa.y, wa.z, wa.w, wb.x, wb.y, wb.z, wb.w};
        #pragma unroll
        for (int hh = 0; hh < 8; hh++) {
            u64 wp = pack2(wf[hh], wf[hh]);
            a[hh][0] = fma2(wp, xa.x, a[hh][0]);
            a[hh][1] = fma2(wp, xa.y, a[hh][1]);
            a[hh][2] = fma2(wp, xb.x, a[hh][2]);
            a[hh][3] = fma2(wp, xb.y, a[hh][3]);
        }
    }
    // epilogue 2: bias, store g_a1[h][pt], BN2 stats
    #pragma unroll
    for (int hh = 0; hh < 8; hh++) {
        int h = h0 + hh;
        float bias = sba1[h];
        float vv[8];
        #pragma unroll
        for (int j = 0; j < 4; j++) {
            float2 u = unpack2(a[hh][j]);
            vv[j*2+0] = u.x + bias;
            vv[j*2+1] = u.y + bias;
        }
        float s = 0.f, s2 = 0.f;
        #pragma unroll
        for (int j = 0; j < 8; j++) { s += vv[j]; s2 += vv[j]*vv[j]; }
        float* op = &g_a1[(size_t)h*NPTS + p0 + pt0];
        *(float4*)op       = make_float4(vv[0], vv[1], vv[2], vv[3]);
        *(float4*)(op + 4) = make_float4(vv[4], vv[5], vv[6], vv[7]);
        #pragma unroll
        for (int off = 8; off > 0; off >>= 1) {
            s  += __shfl_xor_sync(0xffffffffu, s, off);
            s2 += __shfl_xor_sync(0xffffffffu, s2, off);
        }
        if (pg == 0) {
            atomicAdd(&g_sum2[h], (double)s);
            atomicAdd(&g_sq2[h],  (double)s2);
        }
    }
}

// ---------------- a2 = Wa2 @ relu(BN2(a1)) + ba2 ; softmax; aggregate ------
// 128 threads, 8d x 8pt tiles, 4 chunks of 64 h.
__global__ __launch_bounds__(128, 4)
void a2_softagg_kernel(const float* __restrict__ ba2,
                       const float* __restrict__ ga,  const float* __restrict__ bta) {
    extern __shared__ float sm7[];
    float* sW   = sm7;             // [64 hl][64 d] chunk ; sOut overlays sm7
    float* sA   = sW + 64*Dc;      // [64 hl][128 pt]
    float* ssc  = sA + 64*128;     // 256
    float* ssh2 = ssc + Hc;        // 256
    float* sba2 = ssh2 + Hc;       // 64
    int t = threadIdx.x;
    int p0 = blockIdx.x * 128;
    int b  = p0 >> 15;
    for (int i = t; i < Hc; i += 128) {
        const double inv = 1.0 / (double)NPTS;
        double m = g_sum2[i]*inv;
        double v = g_sq2[i]*inv - m*m;
        float rs = rsqrtf((float)v + EPSf);
        float sc = ga[i] * rs;
        ssc[i] = sc;
        ssh2[i] = bta[i] - (float)m*sc;
    }
    if (t < Dc) sba2[t] = ba2[t];
    int og = t >> 4, pg = t & 15;
    int d0 = og*8, pt0 = pg*8;
    u64 acc[8][4];
    #pragma unroll
    for (int q = 0; q < 8; q++)
        #pragma unroll
        for (int j = 0; j < 4; j++) acc[q][j] = 0ull;
    for (int ks = 0; ks < 4; ks++) {
        int h0k = ks*64;
        __syncthreads();
        for (int i = t; i < 1024; i += 128)
            ((float4*)sW)[i] = ((const float4*)(g_Wa2t + (size_t)h0k*Dc))[i];
        for (int f = t; f < 2048; f += 128) {
            int hl = f >> 5, pt4 = f & 31;
            int h = h0k + hl;
            float4 v = *(const float4*)&g_a1[(size_t)h*NPTS + p0 + pt4*4];
            float sc = ssc[h], sh = ssh2[h];
            float4 o = make_float4(fmaxf(fmaf(v.x, sc, sh), 0.f),
                                   fmaxf(fmaf(v.y, sc, sh), 0.f),
                                   fmaxf(fmaf(v.z, sc, sh), 0.f),
                                   fmaxf(fmaf(v.w, sc, sh), 0.f));
            *(float4*)&sA[hl*128 + pt4*4] = o;
        }
        __syncthreads();
        for (int hl = 0; hl < 64; hl++) {
            ulonglong2 xa = *(const ulonglong2*)&sA[hl*128 + pt0];
            ulonglong2 xb = *(const ulonglong2*)&sA[hl*128 + pt0 + 4];
            float4 wa = *(const float4*)&sW[hl*Dc + d0];
            float4 wb = *(const float4*)&sW[hl*Dc + d0 + 4];
            float wf[8] = {wa.x, wa.y, wa.z, wa.w, wb.x, wb.y, wb.z, wb.w};
            #pragma unroll
            for (int q = 0; q < 8; q++) {
                u64 wp = pack2(wf[q], wf[q]);
                acc[q][0] = fma2(wp, xa.x, acc[q][0]);
                acc[q][1] = fma2(wp, xa.y, acc[q][1]);
                acc[q][2] = fma2(wp, xb.x, acc[q][2]);
                acc[q][3] = fma2(wp, xb.y, acc[q][3]);
            }
        }
    }
    __syncthreads();
    float* sOut = sm7;    // [128 pt][65]
    #pragma unroll
    for (int q = 0; q < 8; q++) {
        float bb = sba2[d0+q];
        float vv[8];
        #pragma unroll
        for (int j = 0; j < 4; j++) {
            float2 u = unpack2(acc[q][j]);
            vv[j*2+0] = u.x + bb; vv[j*2+1] = u.y + bb;
        }
        #pragma unroll
        for (int p = 0; p < 8; p++)
            sOut[(pt0+p)*65 + d0+q] = vv[p];
    }
    __syncthreads();
    int d  = t & 63;
    for (int nl = (t >> 6); nl < 8; nl += 2) {
        int base = nl*16;
        float av[Kc];
        float mx = -3.4e38f;
        #pragma unroll
        for (int k = 0; k < Kc; k++) {
            av[k] = sOut[(base + k)*65 + d];
            mx = fmaxf(mx, av[k]);
        }
        float sum = 0.f;
        #pragma unroll
        for (int k = 0; k < Kc; k++) { av[k] = __expf(av[k] - mx); sum += av[k]; }
        float inv = 1.f / sum;
        const int* ip = g_idx + p0 + base;
        float agg = 0.f;
        #pragma unroll
        for (int k = 0; k < Kc; k++) {
            int iv = ip[k];
            float vg = g_v[((size_t)b*Mc + iv)*Dc + d];
            float pe = g_pe[(size_t)(p0 + base + k)*Dc + d];
            agg = fmaf(av[k]*inv, vg + pe, agg);
        }
        int bn = (p0 >> 4) + nl;
        g_agg[(size_t)bn*Dc + d] = agg;
    }
}

// ---------------- out = We @ agg + be + fq ---------------------------------
__global__ __launch_bounds__(512, 2)
void final_kernel(const float* __restrict__ be,
                  const float* __restrict__ fq, float* __restrict__ out) {
    extern __shared__ float sm8[];
    float* sWet = sm8;             // [64 d][128 c] transposed
    float* sG  = sWet + Dc*Cc;     // [64 d][128 n]
    float* sbe = sG + Dc*128;      // 128
    int t = threadIdx.x;
    int b = blockIdx.y;
    int nblk = blockIdx.x * 128;
    for (int i = t; i < Cc*Dc/4; i += 512) ((float4*)sWet)[i] = ((const float4*)g_Wet)[i];
    if (t < Cc) sbe[t] = be[t];
    for (int f = t; f < 2048; f += 512) {
        int d4 = f >> 7, nl = f & 127;
        float4 v = *(const float4*)&g_agg[((size_t)b*Nc + nblk + nl)*Dc + d4*4];
        int d = d4*4;
        sG[(d+0)*128 + nl] = v.x;
        sG[(d+1)*128 + nl] = v.y;
        sG[(d+2)*128 + nl] = v.z;
        sG[(d+3)*128 + nl] = v.w;
    }
    __syncthreads();
    int og = t >> 4, pg = t & 15;
    int c0 = og*4, n0 = pg*8;
    u64 acc[4][4];
    #pragma unroll
    for (int q = 0; q < 4; q++)
        #pragma unroll
        for (int j = 0; j < 4; j++) acc[q][j] = 0ull;
    #pragma unroll 2
    for (int e = 0; e < Dc; e++) {
        ulonglong2 xa = *(const ulonglong2*)&sG[e*128 + n0];
        ulonglong2 xb = *(const ulonglong2*)&sG[e*128 + n0 + 4];
        float4 w4 = *(const float4*)&sWet[e*Cc + c0];
        float wf[4] = {w4.x, w4.y, w4.z, w4.w};
        #pragma unroll
        for (int q = 0; q < 4; q++) {
            u64 wp = pack2(wf[q], wf[q]);
            acc[q][0] = fma2(wp, xa.x, acc[q][0]);
            acc[q][1] = fma2(wp, xa.y, acc[q][1]);
            acc[q][2] = fma2(wp, xb.x, acc[q][2]);
            acc[q][3] = fma2(wp, xb.y, acc[q][3]);
        }
    }
    #pragma unroll
    for (int q = 0; q < 4; q++) {
        int c = c0 + q;
        float bc = sbe[c];
        float vv[8];
        #pragma unroll
        for (int j = 0; j < 4; j++) {
            float2 u = unpack2(acc[q][j]);
            vv[j*2+0] = u.x; vv[j*2+1] = u.y;
        }
        size_t o = (size_t)b*Cc*Nc + (size_t)c*Nc + nblk + n0;
        float4 f0 = *(const float4*)&fq[o];
        float4 f1 = *(const float4*)&fq[o + 4];
        *(float4*)&out[o]     = make_float4(vv[0]+bc+f0.x, vv[1]+bc+f0.y,
                                            vv[2]+bc+f0.z, vv[3]+bc+f0.w);
        *(float4*)&out[o + 4] = make_float4(vv[4]+bc+f1.x, vv[5]+bc+f1.y,
                                            vv[6]+bc+f1.z, vv[7]+bc+f1.w);
    }
}

// ---------------- launch -----------------------------------------------------
extern "C" void kernel_launch(void* const* d_in, const int* in_sizes, int n_in,
                              void* d_out, int out_size) {
    const float* pq  = (const float*)d_in[0];
    const float* fq  = (const float*)d_in[1];
    const float* ps  = (const float*)d_in[2];
    const float* fs  = (const float*)d_in[3];
    const float* Wq  = (const float*)d_in[4];  const float* bq  = (const float*)d_in[5];
    const float* Wk  = (const float*)d_in[6];  const float* bk  = (const float*)d_in[7];
    const float* Wv  = (const float*)d_in[8];  const float* bv  = (const float*)d_in[9];
    const float* Wp1 = (const float*)d_in[10]; const float* bp1 = (const float*)d_in[11];
    const float* gp  = (const float*)d_in[12]; const float* btp = (const float*)d_in[13];
    const float* Wp2 = (const float*)d_in[14]; const float* bp2 = (const float*)d_in[15];
    const float* Wa1 = (const float*)d_in[16]; const float* ba1 = (const float*)d_in[17];
    const float* ga  = (const float*)d_in[18]; const float* bta = (const float*)d_in[19];
    const float* Wa2 = (const float*)d_in[20]; const float* ba2 = (const float*)d_in[21];
    const float* We  = (const float*)d_in[22]; const float* be  = (const float*)d_in[23];
    float* out = (float*)d_out;

    const int SMEM_QKV = (Cc*Dc + 32*128 + Dc) * (int)sizeof(float);
    const int SMEM_KNN = 2048*16 + 64*65*4*2;
    const int SMEM_PA  = (16384 + Dc*128 + 3*Dc + Hc) * (int)sizeof(float);
    const int SMEM_A2  = (64*Dc + 64*128 + 2*Hc + Dc) * (int)sizeof(float);
    const int SMEM_FIN = (Dc*Cc + Dc*128 + Cc) * (int)sizeof(float);
    cudaFuncSetAttribute(qkv_kernel,        cudaFuncAttributeMaxDynamicSharedMemorySize, SMEM_QKV);
    cudaFuncSetAttribute(knn_kernel,        cudaFuncAttributeMaxDynamicSharedMemorySize, SMEM_KNN);
    cudaFuncSetAttribute(pe2_a1_kernel,     cudaFuncAttributeMaxDynamicSharedMemorySize, SMEM_PA);
    cudaFuncSetAttribute(a2_softagg_kernel, cudaFuncAttributeMaxDynamicSharedMemorySize, SMEM_A2);
    cudaFuncSetAttribute(final_kernel,      cudaFuncAttributeMaxDynamicSharedMemorySize, SMEM_FIN);

    prep_kernel<<<dim3(16, 7), 256>>>(Wq, Wk, Wv, Wp2, Wa1, Wa2, We);
    qkv_kernel<<<dim3(Nc/128, 12), 512, SMEM_QKV>>>(fq, fs, bq, bk, bv);
    knn_kernel<<<dim3(Nc/64, Bc), 256, SMEM_KNN>>>(pq, ps);
    pe1_stats_kernel<<<NPTS/256, 256>>>(pq, ps, Wp1, bp1);
    pe2_a1_kernel<<<NPTS/128, 512, SMEM_PA>>>(bp2, gp, btp, ba1);
    a2_softagg_kernel<<<NPTS/128, 128, SMEM_A2>>>(ba2, ga, bta);
    final_kernel<<<dim3(Nc/128, Bc), 512, SMEM_FIN>>>(be, fq, out);
}